// round 2
// baseline (speedup 1.0000x reference)
#include <cuda_runtime.h>
#include <cuda_bf16.h>
#include <cstddef>

typedef unsigned long long ull;

#define H    1024
#define BB   8
#define SS   256
#define VV   32000
#define MALL (BB*SS)          // 2048
#define NB_RNN 128
#define WPAD 1028             // 1024 + 4 pad: de-conflicts 4KB row stride in SMEM
#define RNN_SMEM  122880      // > 227KB/2 -> forces 1 CTA/SM (co-residency for grid barrier)
#define SMAX_SMEM ((VV + 64) * 4)

// ------------------------- device scratch (no allocation APIs allowed) -----
__device__ float g_X[MALL * H];       // embedded input, row m = b*S + t
__device__ float g_pre0[MALL * H];    // X@Wi0.T + bi0 + bh0
__device__ float g_Wo0T[H * H];       // Wo0 transposed
__device__ float g_M10[H * H];        // Wi1 @ Wo0
__device__ float g_HS1[MALL * H];     // layer-1 hidden states
__device__ float g_Y[MALL * H];       // HS1@Wo1.T + bo1
__device__ float g_c1[H];             // Wi1@bo0 + bi1 + bh1
__device__ float g_b0[H];             // bi0 + bh0
__device__ float g_h0buf[2 * BB * H]; // ping-pong layer-0 state [slot][b][feat]
__device__ float g_h1buf[2 * BB * H]; // ping-pong layer-1 state
__device__ volatile unsigned g_bar_gen;
__device__ unsigned g_bar_cnt;

// ------------------------- f32x2 helpers (sm_100+ packed fp32) -------------
__device__ __forceinline__ ull ffma2(ull a, ull b, ull c) {
    ull d;
    asm("fma.rn.f32x2 %0, %1, %2, %3;" : "=l"(d) : "l"(a), "l"(b), "l"(c));
    return d;
}
__device__ __forceinline__ ull pack2(float x, float y) {
    ull d;
    asm("mov.b64 %0, {%1, %2};" : "=l"(d) : "f"(x), "f"(y));
    return d;
}
__device__ __forceinline__ float2 unpack2(ull v) {
    float x, y;
    asm("mov.b64 {%0, %1}, %2;" : "=f"(x), "=f"(y) : "l"(v));
    return make_float2(x, y);
}
__device__ __forceinline__ float hsum4(ull a, ull b) {
    float2 x = unpack2(a), y = unpack2(b);
    return (x.x + x.y) + (y.x + y.y);
}
// 16B L2-level load (bypasses L1: required for cross-CTA ping-pong state)
__device__ __forceinline__ ulonglong2 ldcg2(const float* p) {
    ulonglong2 r;
    asm volatile("ld.global.cg.v2.u64 {%0,%1}, [%2];"
                 : "=l"(r.x), "=l"(r.y) : "l"(p));
    return r;
}

// ------------------------- grid barrier (128 co-resident CTAs) -------------
__device__ __forceinline__ void grid_barrier() {
    __threadfence();            // make all threads' prior stores visible (release)
    __syncthreads();
    if (threadIdx.x == 0) {
        unsigned my = g_bar_gen;
        unsigned t = atomicAdd(&g_bar_cnt, 1u);
        if (t == NB_RNN - 1u) {
            g_bar_cnt = 0u;
            __threadfence();
            g_bar_gen = my + 1u;
        } else {
            while (g_bar_gen == my) { __nanosleep(64); }
        }
        __threadfence();        // acquire
    }
    __syncthreads();
}

// ------------------------- embedding gather --------------------------------
__global__ __launch_bounds__(256) void gather_kernel(const int* __restrict__ tokens,
                                                     const float* __restrict__ E) {
    int m = blockIdx.x;                 // m = b*S + t
    int b = m >> 8, t = m & 255;
    int tok = tokens[b * SS + t];
    const float4* src = reinterpret_cast<const float4*>(E + (size_t)tok * H);
    float4* dst = reinterpret_cast<float4*>(g_X + (size_t)m * H);
    dst[threadIdx.x] = __ldg(src + threadIdx.x);   // 256 threads x 4 floats = 1024
}

// ------------------------- Wo0 transpose -----------------------------------
__global__ void transpose_kernel(const float* __restrict__ in) {
    __shared__ float t[32][33];
    int bx = blockIdx.x * 32, by = blockIdx.y * 32;
    int tx = threadIdx.x;
    for (int j = threadIdx.y; j < 32; j += 8)
        t[j][tx] = in[(size_t)(by + j) * H + bx + tx];
    __syncthreads();
    for (int j = threadIdx.y; j < 32; j += 8)
        g_Wo0T[(size_t)(bx + j) * H + by + tx] = t[tx][j];
}

// ------------------------- bias prep: c1, b0 -------------------------------
__global__ __launch_bounds__(256) void prep_kernel(const float* __restrict__ Wi,
                                                   const float* __restrict__ bi,
                                                   const float* __restrict__ bh,
                                                   const float* __restrict__ bo) {
    int w = threadIdx.x >> 5, lane = threadIdx.x & 31;
    int r = blockIdx.x * 8 + w;
    const float* Wi1r = Wi + (size_t)H * H + (size_t)r * H;
    float s = 0.f;
    for (int k = lane; k < H; k += 32) s += Wi1r[k] * bo[k];
    #pragma unroll
    for (int off = 16; off; off >>= 1) s += __shfl_xor_sync(0xffffffffu, s, off);
    if (lane == 0) {
        g_c1[r] = s + bi[H + r] + bh[H + r];
        g_b0[r] = bi[r] + bh[r];
    }
}

// ------------------------- generic NT GEMM, f32x2 inner --------------------
// C[m][n] = bias[n] + sum_k A[m*K+k] * B[n*K+k].  M,N multiples of 128, K of 16.
__global__ __launch_bounds__(256, 2) void gemm_nt(const float* __restrict__ A,
                                                  const float* __restrict__ B,
                                                  const float* __restrict__ bias,
                                                  float* __restrict__ C,
                                                  int M, int N, int K) {
    __shared__ float As[16][136];
    __shared__ float Bs[16][136];
    const int tid = threadIdx.x;
    const int m0 = blockIdx.x * 128, n0 = blockIdx.y * 128;
    const int tx = tid & 15, ty = tid >> 4;
    const int tm = ty * 8, tn = tx * 8;
    const int lr = tid >> 1;            // loader row 0..127
    const int lc = (tid & 1) * 8;       // loader k-offset {0,8}

    ull acc[4][8];
    #pragma unroll
    for (int i = 0; i < 4; i++)
        #pragma unroll
        for (int j = 0; j < 8; j++) acc[i][j] = 0ull;

    const float* Ab = A + (size_t)m0 * K + (size_t)lr * K + lc;
    const float* Bb = B + (size_t)n0 * K + (size_t)lr * K + lc;

    for (int k0 = 0; k0 < K; k0 += 16) {
        float4 a0 = __ldg((const float4*)(Ab + k0));
        float4 a1 = __ldg((const float4*)(Ab + k0 + 4));
        float4 b0 = __ldg((const float4*)(Bb + k0));
        float4 b1 = __ldg((const float4*)(Bb + k0 + 4));
        __syncthreads();
        As[lc + 0][lr] = a0.x; As[lc + 1][lr] = a0.y; As[lc + 2][lr] = a0.z; As[lc + 3][lr] = a0.w;
        As[lc + 4][lr] = a1.x; As[lc + 5][lr] = a1.y; As[lc + 6][lr] = a1.z; As[lc + 7][lr] = a1.w;
        Bs[lc + 0][lr] = b0.x; Bs[lc + 1][lr] = b0.y; Bs[lc + 2][lr] = b0.z; Bs[lc + 3][lr] = b0.w;
        Bs[lc + 4][lr] = b1.x; Bs[lc + 5][lr] = b1.y; Bs[lc + 6][lr] = b1.z; Bs[lc + 7][lr] = b1.w;
        __syncthreads();
        #pragma unroll
        for (int kk = 0; kk < 16; kk++) {
            ulonglong2 a01 = *(const ulonglong2*)&As[kk][tm];
            ulonglong2 a23 = *(const ulonglong2*)&As[kk][tm + 4];
            float4 bva = *(const float4*)&Bs[kk][tn];
            float4 bvb = *(const float4*)&Bs[kk][tn + 4];
            float bv[8] = {bva.x, bva.y, bva.z, bva.w, bvb.x, bvb.y, bvb.z, bvb.w};
            #pragma unroll
            for (int j = 0; j < 8; j++) {
                ull bd = pack2(bv[j], bv[j]);
                acc[0][j] = ffma2(a01.x, bd, acc[0][j]);
                acc[1][j] = ffma2(a01.y, bd, acc[1][j]);
                acc[2][j] = ffma2(a23.x, bd, acc[2][j]);
                acc[3][j] = ffma2(a23.y, bd, acc[3][j]);
            }
        }
    }

    float bvv[8];
    #pragma unroll
    for (int j = 0; j < 8; j++) bvv[j] = bias ? bias[n0 + tn + j] : 0.f;

    #pragma unroll
    for (int mi = 0; mi < 4; ++mi) {
        float r0v[8], r1v[8];
        #pragma unroll
        for (int j = 0; j < 8; j++) {
            float2 p = unpack2(acc[mi][j]);
            r0v[j] = p.x + bvv[j];
            r1v[j] = p.y + bvv[j];
        }
        float* c0 = C + (size_t)(m0 + tm + 2 * mi) * N + n0 + tn;
        float* c1p = c0 + N;
        *(float4*)(c0)      = make_float4(r0v[0], r0v[1], r0v[2], r0v[3]);
        *(float4*)(c0 + 4)  = make_float4(r0v[4], r0v[5], r0v[6], r0v[7]);
        *(float4*)(c1p)     = make_float4(r1v[0], r1v[1], r1v[2], r1v[3]);
        *(float4*)(c1p + 4) = make_float4(r1v[4], r1v[5], r1v[6], r1v[7]);
    }
}

// ------------------------- persistent skewed RNN ---------------------------
// CTA owns features r0..r0+7. SMEM holds its 8 rows of Wh0, M10, Wh1.
// Tick t: phase A computes hs0[t] (t<S); phase B computes hs1[t-1] (t>=1).
// One grid barrier per tick.
__global__ __launch_bounds__(256, 1) void rnn_kernel(const float* __restrict__ Wh,
                                                     const float* __restrict__ pre0) {
    extern __shared__ float sm[];
    float* Wsh = sm;                 // [24][WPAD]
    float* red = sm + 24 * WPAD;     // [3][8][64]
    const int tid = threadIdx.x;
    const int r0 = blockIdx.x * 8;

    // load 24 weight rows into padded SMEM
    for (int idx = tid; idx < 24 * 256; idx += 256) {
        int j = idx >> 8, c = (idx & 255) * 4;
        const float* srow;
        if (j < 8)       srow = Wh + (size_t)(r0 + j) * H;
        else if (j < 16) srow = g_M10 + (size_t)(r0 + j - 8) * H;
        else             srow = Wh + (size_t)H * H + (size_t)(r0 + j - 16) * H;
        *(float4*)(Wsh + j * WPAD + c) = __ldg((const float4*)(srow + c));
    }
    // zero this CTA's slice of the 4 state buffers
    {
        int t = tid;
        int layer = t >> 7, slot = (t >> 6) & 1, b = (t >> 3) & 7, rr = t & 7;
        float* buf = layer ? g_h1buf : g_h0buf;
        buf[slot * (BB * H) + b * H + r0 + rr] = 0.f;
    }
    grid_barrier();

    const int lane = tid & 31, w = tid >> 5;
    const int rl = lane >> 2, bp = (lane & 3) * 2;
    const float* w0p = Wsh + rl * WPAD + w * 128;          // Wh0 row
    const float* w1p = Wsh + (8 + rl) * WPAD + w * 128;    // M10 row
    const float* w2p = Wsh + (16 + rl) * WPAD + w * 128;   // Wh1 row
    const int hoffA = bp * H + w * 128;
    const int hoffB = hoffA + H;
    const int ridx = w * 64 + rl * 8 + bp;

    for (int tick = 0; tick <= SS; ++tick) {
        const float* h0 = g_h0buf + (((tick & 1) ^ 1)) * (BB * H);  // hs0[tick-1]
        const float* h1 = g_h1buf + ((tick & 1)) * (BB * H);        // hs1[tick-2]
        const bool doA = (tick < SS), doB = (tick >= 1);

        ull m0a0 = 0, m0a1 = 0, m0b0 = 0, m0b1 = 0;
        ull m1a0 = 0, m1a1 = 0, m1b0 = 0, m1b1 = 0;
        ull m2a0 = 0, m2a1 = 0, m2b0 = 0, m2b1 = 0;

        if (doA && doB) {
            #pragma unroll 4
            for (int i = 0; i < 32; ++i) {
                ulonglong2 w0 = *(const ulonglong2*)(w0p + i * 4);
                ulonglong2 w1 = *(const ulonglong2*)(w1p + i * 4);
                ulonglong2 w2 = *(const ulonglong2*)(w2p + i * 4);
                ulonglong2 h0a = ldcg2(h0 + hoffA + i * 4);
                ulonglong2 h0b = ldcg2(h0 + hoffB + i * 4);
                ulonglong2 h1a = ldcg2(h1 + hoffA + i * 4);
                ulonglong2 h1b = ldcg2(h1 + hoffB + i * 4);
                m0a0 = ffma2(w0.x, h0a.x, m0a0); m0a1 = ffma2(w0.y, h0a.y, m0a1);
                m0b0 = ffma2(w0.x, h0b.x, m0b0); m0b1 = ffma2(w0.y, h0b.y, m0b1);
                m1a0 = ffma2(w1.x, h0a.x, m1a0); m1a1 = ffma2(w1.y, h0a.y, m1a1);
                m1b0 = ffma2(w1.x, h0b.x, m1b0); m1b1 = ffma2(w1.y, h0b.y, m1b1);
                m2a0 = ffma2(w2.x, h1a.x, m2a0); m2a1 = ffma2(w2.y, h1a.y, m2a1);
                m2b0 = ffma2(w2.x, h1b.x, m2b0); m2b1 = ffma2(w2.y, h1b.y, m2b1);
            }
        } else if (doA) {  // tick 0
            #pragma unroll 4
            for (int i = 0; i < 32; ++i) {
                ulonglong2 w0 = *(const ulonglong2*)(w0p + i * 4);
                ulonglong2 h0a = ldcg2(h0 + hoffA + i * 4);
                ulonglong2 h0b = ldcg2(h0 + hoffB + i * 4);
                m0a0 = ffma2(w0.x, h0a.x, m0a0); m0a1 = ffma2(w0.y, h0a.y, m0a1);
                m0b0 = ffma2(w0.x, h0b.x, m0b0); m0b1 = ffma2(w0.y, h0b.y, m0b1);
            }
        } else {           // tick SS
            #pragma unroll 4
            for (int i = 0; i < 32; ++i) {
                ulonglong2 w1 = *(const ulonglong2*)(w1p + i * 4);
                ulonglong2 w2 = *(const ulonglong2*)(w2p + i * 4);
                ulonglong2 h0a = ldcg2(h0 + hoffA + i * 4);
                ulonglong2 h0b = ldcg2(h0 + hoffB + i * 4);
                ulonglong2 h1a = ldcg2(h1 + hoffA + i * 4);
                ulonglong2 h1b = ldcg2(h1 + hoffB + i * 4);
                m1a0 = ffma2(w1.x, h0a.x, m1a0); m1a1 = ffma2(w1.y, h0a.y, m1a1);
                m1b0 = ffma2(w1.x, h0b.x, m1b0); m1b1 = ffma2(w1.y, h0b.y, m1b1);
                m2a0 = ffma2(w2.x, h1a.x, m2a0); m2a1 = ffma2(w2.y, h1a.y, m2a1);
                m2b0 = ffma2(w2.x, h1b.x, m2b0); m2b1 = ffma2(w2.y, h1b.y, m2b1);
            }
        }

        if (doA) {
            red[ridx]     = hsum4(m0a0, m0a1);
            red[ridx + 1] = hsum4(m0b0, m0b1);
        }
        if (doB) {
            red[512 + ridx]      = hsum4(m1a0, m1a1);
            red[512 + ridx + 1]  = hsum4(m1b0, m1b1);
            red[1024 + ridx]     = hsum4(m2a0, m2a1);
            red[1024 + ridx + 1] = hsum4(m2b0, m2b1);
        }
        __syncthreads();

        if (tid < 64) {
            if (doA) {
                int r = tid >> 3, b = tid & 7;
                float s = 0.f;
                #pragma unroll
                for (int ww = 0; ww < 8; ++ww) s += red[ww * 64 + tid];
                float v = tanhf(pre0[(size_t)(b * SS + tick) * H + r0 + r] + s);
                __stcg(&g_h0buf[(tick & 1) * (BB * H) + b * H + r0 + r], v);
            }
        } else if (tid < 128) {
            if (doB) {
                int j = tid - 64;
                int r = j >> 3, b = j & 7;
                float s1 = 0.f, s2 = 0.f;
                #pragma unroll
                for (int ww = 0; ww < 8; ++ww) {
                    s1 += red[512 + ww * 64 + j];
                    s2 += red[1024 + ww * 64 + j];
                }
                float v = tanhf(g_c1[r0 + r] + s1 + s2);
                __stcg(&g_h1buf[((tick & 1) ^ 1) * (BB * H) + b * H + r0 + r], v);
                g_HS1[(size_t)(b * SS + tick - 1) * H + r0 + r] = v;
            }
        }
        grid_barrier();
    }
}

// ------------------------- fused per-row softmax ---------------------------
__global__ __launch_bounds__(256) void softmax_kernel(float* __restrict__ logits) {
    extern __shared__ float sh[];
    float* row = sh;            // [32000]
    float* red = sh + VV;       // [64]
    const int tid = threadIdx.x;
    float4* src = (float4*)(logits + (size_t)blockIdx.x * VV);

    float mx = -3.4e38f;
    for (int i = tid; i < VV / 4; i += 256) {
        float4 v = src[i];
        ((float4*)row)[i] = v;
        mx = fmaxf(mx, fmaxf(fmaxf(v.x, v.y), fmaxf(v.z, v.w)));
    }
    #pragma unroll
    for (int o = 16; o; o >>= 1) mx = fmaxf(mx, __shfl_xor_sync(0xffffffffu, mx, o));
    if ((tid & 31) == 0) red[tid >> 5] = mx;
    __syncthreads();
    if (tid == 0) {
        float m2 = red[0];
        for (int i = 1; i < 8; i++) m2 = fmaxf(m2, red[i]);
        red[32] = m2;
    }
    __syncthreads();
    float M = red[32];

    float s = 0.f;
    for (int i = tid; i < VV; i += 256) {
        float e = __expf(row[i] - M);
        row[i] = e;
        s += e;
    }
    #pragma unroll
    for (int o = 16; o; o >>= 1) s += __shfl_xor_sync(0xffffffffu, s, o);
    if ((tid & 31) == 0) red[tid >> 5] = s;
    __syncthreads();
    if (tid == 0) {
        float t = 0.f;
        for (int i = 0; i < 8; i++) t += red[i];
        red[33] = 1.0f / t;
    }
    __syncthreads();
    float inv = red[33];

    for (int i = tid; i < VV / 4; i += 256) {
        float4 v = ((float4*)row)[i];
        v.x *= inv; v.y *= inv; v.z *= inv; v.w *= inv;
        src[i] = v;
    }
}

// ------------------------- launch ------------------------------------------
extern "C" void kernel_launch(void* const* d_in, const int* in_sizes, int n_in,
                              void* d_out, int out_size) {
    const int*   tokens = (const int*)d_in[0];
    const float* E  = (const float*)d_in[1];
    const float* Wi = (const float*)d_in[2];
    const float* bi = (const float*)d_in[3];
    const float* Wh = (const float*)d_in[4];
    const float* bh = (const float*)d_in[5];
    const float* Wo = (const float*)d_in[6];
    const float* bo = (const float*)d_in[7];
    float* out = (float*)d_out;

    cudaFuncSetAttribute(rnn_kernel, cudaFuncAttributeMaxDynamicSharedMemorySize, RNN_SMEM);
    cudaFuncSetAttribute(softmax_kernel, cudaFuncAttributeMaxDynamicSharedMemorySize, SMAX_SMEM);

    // resolve device-scratch symbol addresses (host query, not an allocation)
    static float *pX = nullptr, *pPre0, *pWo0T, *pM10, *pHS1, *pY, *pB0;
    if (!pX) {
        cudaGetSymbolAddress((void**)&pX,    g_X);
        cudaGetSymbolAddress((void**)&pPre0, g_pre0);
        cudaGetSymbolAddress((void**)&pWo0T, g_Wo0T);
        cudaGetSymbolAddress((void**)&pM10,  g_M10);
        cudaGetSymbolAddress((void**)&pHS1,  g_HS1);
        cudaGetSymbolAddress((void**)&pY,    g_Y);
        cudaGetSymbolAddress((void**)&pB0,   g_b0);
    }

    gather_kernel<<<MALL, 256>>>(tokens, E);
    transpose_kernel<<<dim3(32, 32), dim3(32, 8)>>>(Wo);         // -> g_Wo0T
    prep_kernel<<<128, 256>>>(Wi, bi, bh, bo);                   // -> g_c1, g_b0
    // pre0 = X @ Wi0.T + (bi0+bh0)
    gemm_nt<<<dim3(16, 8), 256>>>(pX, Wi, pB0, pPre0, MALL, H, H);
    // M10 = Wi1 @ Wo0  (NT with B = Wo0T)
    gemm_nt<<<dim3(8, 8), 256>>>(Wi + (size_t)H * H, pWo0T, nullptr, pM10, H, H, H);
    // skewed recurrence -> g_HS1
    rnn_kernel<<<NB_RNN, 256, RNN_SMEM>>>(Wh, pPre0);
    // Y = HS1 @ Wo1.T + bo1
    gemm_nt<<<dim3(16, 8), 256>>>(pHS1, Wo + (size_t)H * H, bo + H, pY, MALL, H, H);
    // logits = Y @ E.T
    gemm_nt<<<dim3(16, VV / 128), 256>>>(pY, E, nullptr, out, MALL, VV, H);
    // softmax in place
    softmax_kernel<<<MALL, 256, SMAX_SMEM>>>(out);
}

// round 4
// speedup vs baseline: 1.5502x; 1.5502x over previous
#include <cuda_runtime.h>
#include <cuda_bf16.h>
#include <cstddef>
#include <cstdint>

typedef unsigned long long ull;

#define H    1024
#define BB   8
#define SS   256
#define VV   32000
#define MALL (BB*SS)          // 2048
#define NB_RNN 128
#define WPAD 1028
#define RNN_SMEM  122880      // forces 1 CTA/SM (co-residency for grid barrier)
#define SMAX_SMEM ((VV + 64) * 4)

// ------------------------- device scratch ----------------------------------
__device__ float g_X[MALL * H];
__device__ float g_pre0[MALL * H];
__device__ float g_Wo0T[H * H];
__device__ float g_M10[H * H];
__device__ float g_HS1[MALL * H];
__device__ float g_Y[MALL * H];
__device__ float g_c1[H];
__device__ float g_b0[H];
__device__ float g_h0buf[2 * BB * H];
__device__ float g_h1buf[2 * BB * H];
__device__ __nv_bfloat16 g_Eb[(size_t)VV * H];   // 64MB
__device__ __nv_bfloat16 g_Yb[(size_t)MALL * H]; // 4MB
__device__ volatile unsigned g_bar_gen;
__device__ unsigned g_bar_cnt;

// ------------------------- f32x2 helpers -----------------------------------
__device__ __forceinline__ ull ffma2(ull a, ull b, ull c) {
    ull d;
    asm("fma.rn.f32x2 %0, %1, %2, %3;" : "=l"(d) : "l"(a), "l"(b), "l"(c));
    return d;
}
__device__ __forceinline__ ull pack2(float x, float y) {
    ull d;
    asm("mov.b64 %0, {%1, %2};" : "=l"(d) : "f"(x), "f"(y));
    return d;
}
__device__ __forceinline__ float2 unpack2(ull v) {
    float x, y;
    asm("mov.b64 {%0, %1}, %2;" : "=f"(x), "=f"(y) : "l"(v));
    return make_float2(x, y);
}
__device__ __forceinline__ float hsum4(ull a, ull b) {
    float2 x = unpack2(a), y = unpack2(b);
    return (x.x + x.y) + (y.x + y.y);
}
__device__ __forceinline__ ulonglong2 ldcg2(const float* p) {
    ulonglong2 r;
    asm volatile("ld.global.cg.v2.u64 {%0,%1}, [%2];"
                 : "=l"(r.x), "=l"(r.y) : "l"(p));
    return r;
}
__device__ __forceinline__ uint32_t smem_u32(const void* p) {
    uint32_t a;
    asm("{ .reg .u64 t; cvta.to.shared.u64 t, %1; cvt.u32.u64 %0, t; }"
        : "=r"(a) : "l"(p));
    return a;
}
__device__ __forceinline__ void cpasync16(uint32_t dst, const void* src) {
    asm volatile("cp.async.cg.shared.global [%0], [%1], 16;"
                 :: "r"(dst), "l"(src));
}
__device__ __forceinline__ void ldmx4(uint32_t* r, uint32_t addr) {
    asm volatile("ldmatrix.sync.aligned.m8n8.x4.shared.b16 {%0,%1,%2,%3}, [%4];"
                 : "=r"(r[0]), "=r"(r[1]), "=r"(r[2]), "=r"(r[3]) : "r"(addr));
}
__device__ __forceinline__ void mma16816(float* d, const uint32_t* a, const uint32_t* b) {
    asm volatile(
        "mma.sync.aligned.m16n8k16.row.col.f32.bf16.bf16.f32 "
        "{%0,%1,%2,%3}, {%4,%5,%6,%7}, {%8,%9}, {%0,%1,%2,%3};"
        : "+f"(d[0]), "+f"(d[1]), "+f"(d[2]), "+f"(d[3])
        : "r"(a[0]), "r"(a[1]), "r"(a[2]), "r"(a[3]), "r"(b[0]), "r"(b[1]));
}

// ------------------------- grid barrier ------------------------------------
__device__ __forceinline__ void grid_barrier() {
    __threadfence();
    __syncthreads();
    if (threadIdx.x == 0) {
        unsigned my = g_bar_gen;
        unsigned t = atomicAdd(&g_bar_cnt, 1u);
        if (t == NB_RNN - 1u) {
            g_bar_cnt = 0u;
            __threadfence();
            g_bar_gen = my + 1u;
        } else {
            while (g_bar_gen == my) { __nanosleep(64); }
        }
        __threadfence();
    }
    __syncthreads();
}

// ------------------------- embedding gather --------------------------------
__global__ __launch_bounds__(256) void gather_kernel(const int* __restrict__ tokens,
                                                     const float* __restrict__ E) {
    int m = blockIdx.x;
    int b = m >> 8, t = m & 255;
    int tok = tokens[b * SS + t];
    const float4* src = reinterpret_cast<const float4*>(E + (size_t)tok * H);
    float4* dst = reinterpret_cast<float4*>(g_X + (size_t)m * H);
    dst[threadIdx.x] = __ldg(src + threadIdx.x);
}

// ------------------------- Wo0 transpose -----------------------------------
__global__ void transpose_kernel(const float* __restrict__ in) {
    __shared__ float t[32][33];
    int bx = blockIdx.x * 32, by = blockIdx.y * 32;
    int tx = threadIdx.x;
    for (int j = threadIdx.y; j < 32; j += 8)
        t[j][tx] = in[(size_t)(by + j) * H + bx + tx];
    __syncthreads();
    for (int j = threadIdx.y; j < 32; j += 8)
        g_Wo0T[(size_t)(bx + j) * H + by + tx] = t[tx][j];
}

// ------------------------- bias prep ---------------------------------------
__global__ __launch_bounds__(256) void prep_kernel(const float* __restrict__ Wi,
                                                   const float* __restrict__ bi,
                                                   const float* __restrict__ bh,
                                                   const float* __restrict__ bo) {
    int w = threadIdx.x >> 5, lane = threadIdx.x & 31;
    int r = blockIdx.x * 8 + w;
    const float* Wi1r = Wi + (size_t)H * H + (size_t)r * H;
    float s = 0.f;
    for (int k = lane; k < H; k += 32) s += Wi1r[k] * bo[k];
    #pragma unroll
    for (int off = 16; off; off >>= 1) s += __shfl_xor_sync(0xffffffffu, s, off);
    if (lane == 0) {
        g_c1[r] = s + bi[H + r] + bh[H + r];
        g_b0[r] = bi[r] + bh[r];
    }
}

// ------------------------- fp32 -> bf16 convert ----------------------------
__global__ __launch_bounds__(256) void conv_bf16(const float* __restrict__ in,
                                                 __nv_bfloat16* __restrict__ out,
                                                 int n8) {
    int i = blockIdx.x * 256 + threadIdx.x;
    if (i >= n8) return;
    const float4* p = (const float4*)in + (size_t)i * 2;
    float4 a = __ldg(p), b = __ldg(p + 1);
    __nv_bfloat162 r0 = __float22bfloat162_rn(make_float2(a.x, a.y));
    __nv_bfloat162 r1 = __float22bfloat162_rn(make_float2(a.z, a.w));
    __nv_bfloat162 r2 = __float22bfloat162_rn(make_float2(b.x, b.y));
    __nv_bfloat162 r3 = __float22bfloat162_rn(make_float2(b.z, b.w));
    uint4 u;
    u.x = *(uint32_t*)&r0; u.y = *(uint32_t*)&r1;
    u.z = *(uint32_t*)&r2; u.w = *(uint32_t*)&r3;
    ((uint4*)out)[i] = u;
}

// ------------------------- SIMT NT GEMM (recurrent-path, fp32) -------------
__global__ __launch_bounds__(256, 2) void gemm_nt(const float* __restrict__ A,
                                                  const float* __restrict__ B,
                                                  const float* __restrict__ bias,
                                                  float* __restrict__ C,
                                                  int M, int N, int K) {
    __shared__ float As[16][136];
    __shared__ float Bs[16][136];
    const int tid = threadIdx.x;
    const int m0 = blockIdx.x * 128, n0 = blockIdx.y * 128;
    const int tx = tid & 15, ty = tid >> 4;
    const int tm = ty * 8, tn = tx * 8;
    const int lr = tid >> 1;
    const int lc = (tid & 1) * 8;

    ull acc[4][8];
    #pragma unroll
    for (int i = 0; i < 4; i++)
        #pragma unroll
        for (int j = 0; j < 8; j++) acc[i][j] = 0ull;

    const float* Ab = A + (size_t)m0 * K + (size_t)lr * K + lc;
    const float* Bb = B + (size_t)n0 * K + (size_t)lr * K + lc;

    for (int k0 = 0; k0 < K; k0 += 16) {
        float4 a0 = __ldg((const float4*)(Ab + k0));
        float4 a1 = __ldg((const float4*)(Ab + k0 + 4));
        float4 b0 = __ldg((const float4*)(Bb + k0));
        float4 b1 = __ldg((const float4*)(Bb + k0 + 4));
        __syncthreads();
        As[lc + 0][lr] = a0.x; As[lc + 1][lr] = a0.y; As[lc + 2][lr] = a0.z; As[lc + 3][lr] = a0.w;
        As[lc + 4][lr] = a1.x; As[lc + 5][lr] = a1.y; As[lc + 6][lr] = a1.z; As[lc + 7][lr] = a1.w;
        Bs[lc + 0][lr] = b0.x; Bs[lc + 1][lr] = b0.y; Bs[lc + 2][lr] = b0.z; Bs[lc + 3][lr] = b0.w;
        Bs[lc + 4][lr] = b1.x; Bs[lc + 5][lr] = b1.y; Bs[lc + 6][lr] = b1.z; Bs[lc + 7][lr] = b1.w;
        __syncthreads();
        #pragma unroll
        for (int kk = 0; kk < 16; kk++) {
            ulonglong2 a01 = *(const ulonglong2*)&As[kk][tm];
            ulonglong2 a23 = *(const ulonglong2*)&As[kk][tm + 4];
            float4 bva = *(const float4*)&Bs[kk][tn];
            float4 bvb = *(const float4*)&Bs[kk][tn + 4];
            float bv[8] = {bva.x, bva.y, bva.z, bva.w, bvb.x, bvb.y, bvb.z, bvb.w};
            #pragma unroll
            for (int j = 0; j < 8; j++) {
                ull bd = pack2(bv[j], bv[j]);
                acc[0][j] = ffma2(a01.x, bd, acc[0][j]);
                acc[1][j] = ffma2(a01.y, bd, acc[1][j]);
                acc[2][j] = ffma2(a23.x, bd, acc[2][j]);
                acc[3][j] = ffma2(a23.y, bd, acc[3][j]);
            }
        }
    }

    float bvv[8];
    #pragma unroll
    for (int j = 0; j < 8; j++) bvv[j] = bias ? bias[n0 + tn + j] : 0.f;

    #pragma unroll
    for (int mi = 0; mi < 4; ++mi) {
        float r0v[8], r1v[8];
        #pragma unroll
        for (int j = 0; j < 8; j++) {
            float2 p = unpack2(acc[mi][j]);
            r0v[j] = p.x + bvv[j];
            r1v[j] = p.y + bvv[j];
        }
        float* c0 = C + (size_t)(m0 + tm + 2 * mi) * N + n0 + tn;
        float* c1p = c0 + N;
        *(float4*)(c0)      = make_float4(r0v[0], r0v[1], r0v[2], r0v[3]);
        *(float4*)(c0 + 4)  = make_float4(r0v[4], r0v[5], r0v[6], r0v[7]);
        *(float4*)(c1p)     = make_float4(r1v[0], r1v[1], r1v[2], r1v[3]);
        *(float4*)(c1p + 4) = make_float4(r1v[4], r1v[5], r1v[6], r1v[7]);
    }
}

// ------------------------- bf16 mma.sync logits GEMM -----------------------
// C[2048,32000] = Yb[2048,1024] @ Eb[32000,1024]^T
// BM=128, BN=128, BK=32; 8 warps (2x4), warp tile 64x32; 2-stage cp.async.
#define LPITCH 40            // bf16 elems per smem row (32 + 8 pad)
#define LPB    80            // bytes per row
#define TILEB  10240         // one 128x40 bf16 buffer
__global__ __launch_bounds__(256, 2) void gemm_bf16_mma(
    const __nv_bfloat16* __restrict__ Yb,
    const __nv_bfloat16* __restrict__ Eb,
    float* __restrict__ out)
{
    __shared__ __align__(16) char smem[4 * TILEB];  // A0 A1 B0 B1
    const uint32_t sb = smem_u32(smem);
    const int tid = threadIdx.x;
    const int m0 = blockIdx.x * 128, n0 = blockIdx.y * 128;

    const int lrow = tid >> 1, lhalf = (tid & 1) * 16;  // loader: row, k-elem offset
    const __nv_bfloat16* Ag = Yb + (size_t)(m0 + lrow) * H + lhalf;
    const __nv_bfloat16* Bg = Eb + (size_t)(n0 + lrow) * H + lhalf;
    const uint32_t sdst = (uint32_t)lrow * LPB + (uint32_t)lhalf * 2;

    float acc[4][4][4];
    #pragma unroll
    for (int i = 0; i < 4; i++)
        #pragma unroll
        for (int j = 0; j < 4; j++)
            #pragma unroll
            for (int q = 0; q < 4; q++) acc[i][j][q] = 0.f;

    const int w = tid >> 5, lane = tid & 31;
    const int wm = (w >> 2) * 64, wn = (w & 3) * 32;
    // ldmatrix lane addressing
    const int a_row = wm + ((lane >> 3) & 1) * 8 + (lane & 7);
    const int a_col8 = ((lane >> 4) & 1) * 8;            // k sub-chunk
    const int b_row = wn + ((lane >> 4) & 1) * 8 + (lane & 7);
    const int b_col8 = ((lane >> 3) & 1) * 8;

    // prologue: load k-iter 0 into buffer 0
    {
        cpasync16(sb + sdst, Ag);
        cpasync16(sb + sdst + 16, Ag + 8);
        cpasync16(sb + 2 * TILEB + sdst, Bg);
        cpasync16(sb + 2 * TILEB + sdst + 16, Bg + 8);
        asm volatile("cp.async.commit_group;" ::: "memory");
    }

    for (int it = 0; it < 32; ++it) {
        if (it + 1 < 32) {
            const uint32_t bo = (uint32_t)((it + 1) & 1) * TILEB;
            const int ko = (it + 1) * 32;
            cpasync16(sb + bo + sdst, Ag + ko);
            cpasync16(sb + bo + sdst + 16, Ag + ko + 8);
            cpasync16(sb + 2 * TILEB + bo + sdst, Bg + ko);
            cpasync16(sb + 2 * TILEB + bo + sdst + 16, Bg + ko + 8);
            asm volatile("cp.async.commit_group;" ::: "memory");
            asm volatile("cp.async.wait_group 1;" ::: "memory");
        } else {
            asm volatile("cp.async.wait_group 0;" ::: "memory");
        }
        __syncthreads();

        const uint32_t sA = sb + (uint32_t)(it & 1) * TILEB;
        const uint32_t sB = sA + 2 * TILEB;
        #pragma unroll
        for (int ks = 0; ks < 2; ++ks) {
            uint32_t af[4][4], bf[4][2];
            #pragma unroll
            for (int mf = 0; mf < 4; ++mf)
                ldmx4(af[mf], sA + (uint32_t)(a_row + mf * 16) * LPB
                              + (uint32_t)(ks * 16 + a_col8) * 2);
            #pragma unroll
            for (int nf2 = 0; nf2 < 2; ++nf2) {
                uint32_t r[4];
                ldmx4(r, sB + (uint32_t)(b_row + nf2 * 16) * LPB
                         + (uint32_t)(ks * 16 + b_col8) * 2);
                bf[nf2 * 2][0] = r[0]; bf[nf2 * 2][1] = r[1];
                bf[nf2 * 2 + 1][0] = r[2]; bf[nf2 * 2 + 1][1] = r[3];
            }
            #pragma unroll
            for (int mf = 0; mf < 4; ++mf)
                #pragma unroll
                for (int nf = 0; nf < 4; ++nf)
                    mma16816(acc[mf][nf], af[mf], bf[nf]);
        }
        __syncthreads();
    }

    // epilogue: direct float2 stores
    const int erow = lane >> 2, ecol = (lane & 3) * 2;
    #pragma unroll
    for (int mf = 0; mf < 4; ++mf) {
        #pragma unroll
        for (int nf = 0; nf < 4; ++nf) {
            float* p0 = out + (size_t)(m0 + wm + mf * 16 + erow) * VV
                            + n0 + wn + nf * 8 + ecol;
            *(float2*)p0 = make_float2(acc[mf][nf][0], acc[mf][nf][1]);
            *(float2*)(p0 + (size_t)8 * VV) = make_float2(acc[mf][nf][2], acc[mf][nf][3]);
        }
    }
}

// ------------------------- persistent skewed RNN ---------------------------
__global__ __launch_bounds__(256, 1) void rnn_kernel(const float* __restrict__ Wh,
                                                     const float* __restrict__ pre0) {
    extern __shared__ float sm[];
    float* Wsh = sm;
    float* red = sm + 24 * WPAD;
    const int tid = threadIdx.x;
    const int r0 = blockIdx.x * 8;

    for (int idx = tid; idx < 24 * 256; idx += 256) {
        int j = idx >> 8, c = (idx & 255) * 4;
        const float* srow;
        if (j < 8)       srow = Wh + (size_t)(r0 + j) * H;
        else if (j < 16) srow = g_M10 + (size_t)(r0 + j - 8) * H;
        else             srow = Wh + (size_t)H * H + (size_t)(r0 + j - 16) * H;
        *(float4*)(Wsh + j * WPAD + c) = __ldg((const float4*)(srow + c));
    }
    {
        int t = tid;
        int layer = t >> 7, slot = (t >> 6) & 1, b = (t >> 3) & 7, rr = t & 7;
        float* buf = layer ? g_h1buf : g_h0buf;
        buf[slot * (BB * H) + b * H + r0 + rr] = 0.f;
    }
    grid_barrier();

    const int lane = tid & 31, w = tid >> 5;
    const int rl = lane >> 2, bp = (lane & 3) * 2;
    const float* w0p = Wsh + rl * WPAD + w * 128;
    const float* w1p = Wsh + (8 + rl) * WPAD + w * 128;
    const float* w2p = Wsh + (16 + rl) * WPAD + w * 128;
    const int hoffA = bp * H + w * 128;
    const int hoffB = hoffA + H;
    const int ridx = w * 64 + rl * 8 + bp;

    for (int tick = 0; tick <= SS; ++tick) {
        const float* h0 = g_h0buf + (((tick & 1) ^ 1)) * (BB * H);
        const float* h1 = g_h1buf + ((tick & 1)) * (BB * H);
        const bool doA = (tick < SS), doB = (tick >= 1);

        ull m0a0 = 0, m0a1 = 0, m0b0 = 0, m0b1 = 0;
        ull m1a0 = 0, m1a1 = 0, m1b0 = 0, m1b1 = 0;
        ull m2a0 = 0, m2a1 = 0, m2b0 = 0, m2b1 = 0;

        if (doA && doB) {
            #pragma unroll 4
            for (int i = 0; i < 32; ++i) {
                ulonglong2 w0 = *(const ulonglong2*)(w0p + i * 4);
                ulonglong2 w1 = *(const ulonglong2*)(w1p + i * 4);
                ulonglong2 w2 = *(const ulonglong2*)(w2p + i * 4);
                ulonglong2 h0a = ldcg2(h0 + hoffA + i * 4);
                ulonglong2 h0b = ldcg2(h0 + hoffB + i * 4);
                ulonglong2 h1a = ldcg2(h1 + hoffA + i * 4);
                ulonglong2 h1b = ldcg2(h1 + hoffB + i * 4);
                m0a0 = ffma2(w0.x, h0a.x, m0a0); m0a1 = ffma2(w0.y, h0a.y, m0a1);
                m0b0 = ffma2(w0.x, h0b.x, m0b0); m0b1 = ffma2(w0.y, h0b.y, m0b1);
                m1a0 = ffma2(w1.x, h0a.x, m1a0); m1a1 = ffma2(w1.y, h0a.y, m1a1);
                m1b0 = ffma2(w1.x, h0b.x, m1b0); m1b1 = ffma2(w1.y, h0b.y, m1b1);
                m2a0 = ffma2(w2.x, h1a.x, m2a0); m2a1 = ffma2(w2.y, h1a.y, m2a1);
                m2b0 = ffma2(w2.x, h1b.x, m2b0); m2b1 = ffma2(w2.y, h1b.y, m2b1);
            }
        } else if (doA) {
            #pragma unroll 4
            for (int i = 0; i < 32; ++i) {
                ulonglong2 w0 = *(const ulonglong2*)(w0p + i * 4);
                ulonglong2 h0a = ldcg2(h0 + hoffA + i * 4);
                ulonglong2 h0b = ldcg2(h0 + hoffB + i * 4);
                m0a0 = ffma2(w0.x, h0a.x, m0a0); m0a1 = ffma2(w0.y, h0a.y, m0a1);
                m0b0 = ffma2(w0.x, h0b.x, m0b0); m0b1 = ffma2(w0.y, h0b.y, m0b1);
            }
        } else {
            #pragma unroll 4
            for (int i = 0; i < 32; ++i) {
                ulonglong2 w1 = *(const ulonglong2*)(w1p + i * 4);
                ulonglong2 w2 = *(const ulonglong2*)(w2p + i * 4);
                ulonglong2 h0a = ldcg2(h0 + hoffA + i * 4);
                ulonglong2 h0b = ldcg2(h0 + hoffB + i * 4);
                ulonglong2 h1a = ldcg2(h1 + hoffA + i * 4);
                ulonglong2 h1b = ldcg2(h1 + hoffB + i * 4);
                m1a0 = ffma2(w1.x, h0a.x, m1a0); m1a1 = ffma2(w1.y, h0a.y, m1a1);
                m1b0 = ffma2(w1.x, h0b.x, m1b0); m1b1 = ffma2(w1.y, h0b.y, m1b1);
                m2a0 = ffma2(w2.x, h1a.x, m2a0); m2a1 = ffma2(w2.y, h1a.y, m2a1);
                m2b0 = ffma2(w2.x, h1b.x, m2b0); m2b1 = ffma2(w2.y, h1b.y, m2b1);
            }
        }

        if (doA) {
            red[ridx]     = hsum4(m0a0, m0a1);
            red[ridx + 1] = hsum4(m0b0, m0b1);
        }
        if (doB) {
            red[512 + ridx]      = hsum4(m1a0, m1a1);
            red[512 + ridx + 1]  = hsum4(m1b0, m1b1);
            red[1024 + ridx]     = hsum4(m2a0, m2a1);
            red[1024 + ridx + 1] = hsum4(m2b0, m2b1);
        }
        __syncthreads();

        if (tid < 64) {
            if (doA) {
                int r = tid >> 3, b = tid & 7;
                float s = 0.f;
                #pragma unroll
                for (int ww = 0; ww < 8; ++ww) s += red[ww * 64 + tid];
                float v = tanhf(pre0[(size_t)(b * SS + tick) * H + r0 + r] + s);
                __stcg(&g_h0buf[(tick & 1) * (BB * H) + b * H + r0 + r], v);
            }
        } else if (tid < 128) {
            if (doB) {
                int j = tid - 64;
                int r = j >> 3, b = j & 7;
                float s1 = 0.f, s2 = 0.f;
                #pragma unroll
                for (int ww = 0; ww < 8; ++ww) {
                    s1 += red[512 + ww * 64 + j];
                    s2 += red[1024 + ww * 64 + j];
                }
                float v = tanhf(g_c1[r0 + r] + s1 + s2);
                __stcg(&g_h1buf[((tick & 1) ^ 1) * (BB * H) + b * H + r0 + r], v);
                g_HS1[(size_t)(b * SS + tick - 1) * H + r0 + r] = v;
            }
        }
        grid_barrier();
    }
}

// ------------------------- fused per-row softmax ---------------------------
__global__ __launch_bounds__(256) void softmax_kernel(float* __restrict__ logits) {
    extern __shared__ float sh[];
    float* row = sh;
    float* red = sh + VV;
    const int tid = threadIdx.x;
    float4* src = (float4*)(logits + (size_t)blockIdx.x * VV);

    float mx = -3.4e38f;
    for (int i = tid; i < VV / 4; i += 256) {
        float4 v = src[i];
        ((float4*)row)[i] = v;
        mx = fmaxf(mx, fmaxf(fmaxf(v.x, v.y), fmaxf(v.z, v.w)));
    }
    #pragma unroll
    for (int o = 16; o; o >>= 1) mx = fmaxf(mx, __shfl_xor_sync(0xffffffffu, mx, o));
    if ((tid & 31) == 0) red[tid >> 5] = mx;
    __syncthreads();
    if (tid == 0) {
        float m2 = red[0];
        for (int i = 1; i < 8; i++) m2 = fmaxf(m2, red[i]);
        red[32] = m2;
    }
    __syncthreads();
    float M = red[32];

    float s = 0.f;
    for (int i = tid; i < VV; i += 256) {
        float e = __expf(row[i] - M);
        row[i] = e;
        s += e;
    }
    #pragma unroll
    for (int o = 16; o; o >>= 1) s += __shfl_xor_sync(0xffffffffu, s, o);
    if ((tid & 31) == 0) red[tid >> 5] = s;
    __syncthreads();
    if (tid == 0) {
        float t = 0.f;
        for (int i = 0; i < 8; i++) t += red[i];
        red[33] = 1.0f / t;
    }
    __syncthreads();
    float inv = red[33];

    for (int i = tid; i < VV / 4; i += 256) {
        float4 v = ((float4*)row)[i];
        v.x *= inv; v.y *= inv; v.z *= inv; v.w *= inv;
        src[i] = v;
    }
}

// ------------------------- launch ------------------------------------------
extern "C" void kernel_launch(void* const* d_in, const int* in_sizes, int n_in,
                              void* d_out, int out_size) {
    const int*   tokens = (const int*)d_in[0];
    const float* E  = (const float*)d_in[1];
    const float* Wi = (const float*)d_in[2];
    const float* bi = (const float*)d_in[3];
    const float* Wh = (const float*)d_in[4];
    const float* bh = (const float*)d_in[5];
    const float* Wo = (const float*)d_in[6];
    const float* bo = (const float*)d_in[7];
    float* out = (float*)d_out;

    cudaFuncSetAttribute(rnn_kernel, cudaFuncAttributeMaxDynamicSharedMemorySize, RNN_SMEM);
    cudaFuncSetAttribute(softmax_kernel, cudaFuncAttributeMaxDynamicSharedMemorySize, SMAX_SMEM);

    static float *pX = nullptr, *pPre0, *pWo0T, *pM10, *pHS1, *pY, *pB0;
    static __nv_bfloat16 *pEb, *pYb;
    if (!pX) {
        cudaGetSymbolAddress((void**)&pX,    g_X);
        cudaGetSymbolAddress((void**)&pPre0, g_pre0);
        cudaGetSymbolAddress((void**)&pWo0T, g_Wo0T);
        cudaGetSymbolAddress((void**)&pM10,  g_M10);
        cudaGetSymbolAddress((void**)&pHS1,  g_HS1);
        cudaGetSymbolAddress((void**)&pY,    g_Y);
        cudaGetSymbolAddress((void**)&pB0,   g_b0);
        cudaGetSymbolAddress((void**)&pEb,   g_Eb);
        cudaGetSymbolAddress((void**)&pYb,   g_Yb);
    }

    gather_kernel<<<MALL, 256>>>(tokens, E);
    transpose_kernel<<<dim3(32, 32), dim3(32, 8)>>>(Wo);
    prep_kernel<<<128, 256>>>(Wi, bi, bh, bo);
    conv_bf16<<<(VV * H / 8 + 255) / 256, 256>>>(E, pEb, VV * H / 8);
    gemm_nt<<<dim3(16, 8), 256>>>(pX, Wi, pB0, pPre0, MALL, H, H);
    gemm_nt<<<dim3(8, 8), 256>>>(Wi + (size_t)H * H, pWo0T, nullptr, pM10, H, H, H);
    rnn_kernel<<<NB_RNN, 256, RNN_SMEM>>>(Wh, pPre0);
    gemm_nt<<<dim3(16, 8), 256>>>(pHS1, Wo + (size_t)H * H, bo + H, pY, MALL, H, H);
    conv_bf16<<<(MALL * H / 8 + 255) / 256, 256>>>(pY, pYb, MALL * H / 8);
    gemm_bf16_mma<<<dim3(MALL / 128, VV / 128), 256>>>(pYb, pEb, out);
    softmax_kernel<<<MALL, 256, SMAX_SMEM>>>(out);
}

// round 5
// speedup vs baseline: 1.6649x; 1.0739x over previous
#include <cuda_runtime.h>
#include <cuda_bf16.h>
#include <cstddef>
#include <cstdint>

typedef unsigned long long ull;

#define H    1024
#define BB   8
#define SS   256
#define VV   32000
#define MALL (BB*SS)          // 2048
#define NB_RNN 128
#define WPAD 1028
#define RNN_SMEM  122880      // forces 1 CTA/SM (co-residency for grid barrier)
#define SMAX_SMEM ((VV + 64) * 4)

// ------------------------- device scratch ----------------------------------
__device__ float g_pre0[MALL * H];
__device__ float g_M10[H * H];
__device__ float g_c1[H];
__device__ float g_b0[H];
__device__ float g_h0buf[2 * BB * H];
__device__ float g_h1buf[2 * BB * H];
__device__ __nv_bfloat16 g_Eb[(size_t)VV * H];    // 64MB
__device__ __nv_bfloat16 g_Xb[MALL * H];          // 4MB  embedded input (bf16)
__device__ __nv_bfloat16 g_Wib[2 * H * H];        // 4MB
__device__ __nv_bfloat16 g_Wo0Tb[H * H];          // 2MB
__device__ __nv_bfloat16 g_Wo1b[H * H];           // 2MB
__device__ __nv_bfloat16 g_HS1b[MALL * H];        // 4MB
__device__ __nv_bfloat16 g_Yb[MALL * H];          // 4MB
__device__ volatile unsigned g_bar_gen;
__device__ unsigned g_bar_cnt;

// ------------------------- f32x2 helpers (RNN path) ------------------------
__device__ __forceinline__ ull ffma2(ull a, ull b, ull c) {
    ull d;
    asm("fma.rn.f32x2 %0, %1, %2, %3;" : "=l"(d) : "l"(a), "l"(b), "l"(c));
    return d;
}
__device__ __forceinline__ float2 unpack2(ull v) {
    float x, y;
    asm("mov.b64 {%0, %1}, %2;" : "=f"(x), "=f"(y) : "l"(v));
    return make_float2(x, y);
}
__device__ __forceinline__ float hsum4(ull a, ull b) {
    float2 x = unpack2(a), y = unpack2(b);
    return (x.x + x.y) + (y.x + y.y);
}
__device__ __forceinline__ ulonglong2 ldcg2(const float* p) {
    ulonglong2 r;
    asm volatile("ld.global.cg.v2.u64 {%0,%1}, [%2];"
                 : "=l"(r.x), "=l"(r.y) : "l"(p));
    return r;
}
__device__ __forceinline__ uint32_t smem_u32(const void* p) {
    uint32_t a;
    asm("{ .reg .u64 t; cvta.to.shared.u64 t, %1; cvt.u32.u64 %0, t; }"
        : "=r"(a) : "l"(p));
    return a;
}
__device__ __forceinline__ void cpasync16(uint32_t dst, const void* src) {
    asm volatile("cp.async.cg.shared.global [%0], [%1], 16;"
                 :: "r"(dst), "l"(src));
}
__device__ __forceinline__ void ldmx4(uint32_t* r, uint32_t addr) {
    asm volatile("ldmatrix.sync.aligned.m8n8.x4.shared.b16 {%0,%1,%2,%3}, [%4];"
                 : "=r"(r[0]), "=r"(r[1]), "=r"(r[2]), "=r"(r[3]) : "r"(addr));
}
__device__ __forceinline__ void mma16816(float* d, const uint32_t* a, const uint32_t* b) {
    asm volatile(
        "mma.sync.aligned.m16n8k16.row.col.f32.bf16.bf16.f32 "
        "{%0,%1,%2,%3}, {%4,%5,%6,%7}, {%8,%9}, {%0,%1,%2,%3};"
        : "+f"(d[0]), "+f"(d[1]), "+f"(d[2]), "+f"(d[3])
        : "r"(a[0]), "r"(a[1]), "r"(a[2]), "r"(a[3]), "r"(b[0]), "r"(b[1]));
}

// fast exp on the fma/alu pipes (valid for |x| < ~80; err ~4e-5 rel)
__device__ __forceinline__ float fexp(float x) {
    float km = fmaf(x, 1.4426950408889634f, 12582912.0f);  // round(t) in mantissa
    int   ik = __float_as_int(km) - 0x4B400000;
    float kf = km - 12582912.0f;
    float f  = fmaf(kf, -0.6931471805599453f, x);
    float p  = fmaf(f, 0.041666668f, 0.16666667f);
    p = fmaf(p, f, 0.5f);
    p = fmaf(p, f, 1.0f);
    p = fmaf(p, f, 1.0f);
    return __int_as_float(__float_as_int(p) + (ik << 23));
}

// ------------------------- grid barrier ------------------------------------
__device__ __forceinline__ void grid_barrier() {
    __threadfence();
    __syncthreads();
    if (threadIdx.x == 0) {
        unsigned my = g_bar_gen;
        unsigned t = atomicAdd(&g_bar_cnt, 1u);
        if (t == NB_RNN - 1u) {
            g_bar_cnt = 0u;
            __threadfence();
            g_bar_gen = my + 1u;
        } else {
            while (g_bar_gen == my) { __nanosleep(64); }
        }
        __threadfence();
    }
    __syncthreads();
}

// ------------------------- embedding gather (emit bf16) --------------------
__global__ __launch_bounds__(256) void gather_kernel(const int* __restrict__ tokens,
                                                     const float* __restrict__ E) {
    int m = blockIdx.x;
    int b = m >> 8, t = m & 255;
    int tok = tokens[b * SS + t];
    float4 v = __ldg((const float4*)(E + (size_t)tok * H) + threadIdx.x);
    __nv_bfloat162 lo = __float22bfloat162_rn(make_float2(v.x, v.y));
    __nv_bfloat162 hi = __float22bfloat162_rn(make_float2(v.z, v.w));
    uint2 u;
    u.x = *(uint32_t*)&lo; u.y = *(uint32_t*)&hi;
    ((uint2*)(g_Xb + (size_t)m * H))[threadIdx.x] = u;
}

// ------------------------- Wo0 transpose -> bf16 ---------------------------
__global__ void transpose_kernel(const float* __restrict__ in) {
    __shared__ float t[32][33];
    int bx = blockIdx.x * 32, by = blockIdx.y * 32;
    int tx = threadIdx.x;
    for (int j = threadIdx.y; j < 32; j += 8)
        t[j][tx] = in[(size_t)(by + j) * H + bx + tx];
    __syncthreads();
    for (int j = threadIdx.y; j < 32; j += 8)
        g_Wo0Tb[(size_t)(bx + j) * H + by + tx] = __float2bfloat16(t[tx][j]);
}

// ------------------------- bias prep ---------------------------------------
__global__ __launch_bounds__(256) void prep_kernel(const float* __restrict__ Wi,
                                                   const float* __restrict__ bi,
                                                   const float* __restrict__ bh,
                                                   const float* __restrict__ bo) {
    int w = threadIdx.x >> 5, lane = threadIdx.x & 31;
    int r = blockIdx.x * 8 + w;
    const float* Wi1r = Wi + (size_t)H * H + (size_t)r * H;
    float s = 0.f;
    for (int k = lane; k < H; k += 32) s += Wi1r[k] * bo[k];
    #pragma unroll
    for (int off = 16; off; off >>= 1) s += __shfl_xor_sync(0xffffffffu, s, off);
    if (lane == 0) {
        g_c1[r] = s + bi[H + r] + bh[H + r];
        g_b0[r] = bi[r] + bh[r];
    }
}

// ------------------------- fp32 -> bf16 convert ----------------------------
__global__ __launch_bounds__(256) void conv_bf16(const float* __restrict__ in,
                                                 __nv_bfloat16* __restrict__ out,
                                                 int n8) {
    int i = blockIdx.x * 256 + threadIdx.x;
    if (i >= n8) return;
    const float4* p = (const float4*)in + (size_t)i * 2;
    float4 a = __ldg(p), b = __ldg(p + 1);
    __nv_bfloat162 r0 = __float22bfloat162_rn(make_float2(a.x, a.y));
    __nv_bfloat162 r1 = __float22bfloat162_rn(make_float2(a.z, a.w));
    __nv_bfloat162 r2 = __float22bfloat162_rn(make_float2(b.x, b.y));
    __nv_bfloat162 r3 = __float22bfloat162_rn(make_float2(b.z, b.w));
    uint4 u;
    u.x = *(uint32_t*)&r0; u.y = *(uint32_t*)&r1;
    u.z = *(uint32_t*)&r2; u.w = *(uint32_t*)&r3;
    ((uint4*)out)[i] = u;
}

// ------------------------- generalized bf16 mma.sync NT GEMM ---------------
// C[m][n] = bias[n] + sum_k A[m*K+k]*B[n*K+k]; M,N mult of 128, K mult of 32.
// Output fp32 (Cf) or bf16 (Cb) with row stride ldc.
#define LPITCH 40
#define LPB    80
#define TILEB  10240
__global__ __launch_bounds__(256, 2) void gemm_bf16_mma(
    const __nv_bfloat16* __restrict__ A,
    const __nv_bfloat16* __restrict__ B,
    const float* __restrict__ bias,
    float* __restrict__ Cf,
    __nv_bfloat16* __restrict__ Cb,
    int K, int ldc)
{
    __shared__ __align__(16) char smem[4 * TILEB];  // A0 A1 B0 B1
    const uint32_t sb = smem_u32(smem);
    const int tid = threadIdx.x;
    const int m0 = blockIdx.x * 128, n0 = blockIdx.y * 128;
    const int niter = K >> 5;

    const int lrow = tid >> 1, lhalf = (tid & 1) * 16;
    const __nv_bfloat16* Ag = A + (size_t)(m0 + lrow) * K + lhalf;
    const __nv_bfloat16* Bg = B + (size_t)(n0 + lrow) * K + lhalf;
    const uint32_t sdst = (uint32_t)lrow * LPB + (uint32_t)lhalf * 2;

    float acc[4][4][4];
    #pragma unroll
    for (int i = 0; i < 4; i++)
        #pragma unroll
        for (int j = 0; j < 4; j++)
            #pragma unroll
            for (int q = 0; q < 4; q++) acc[i][j][q] = 0.f;

    const int w = tid >> 5, lane = tid & 31;
    const int wm = (w >> 2) * 64, wn = (w & 3) * 32;
    const int a_row = wm + ((lane >> 3) & 1) * 8 + (lane & 7);
    const int a_col8 = ((lane >> 4) & 1) * 8;
    const int b_row = wn + ((lane >> 4) & 1) * 8 + (lane & 7);
    const int b_col8 = ((lane >> 3) & 1) * 8;

    {
        cpasync16(sb + sdst, Ag);
        cpasync16(sb + sdst + 16, Ag + 8);
        cpasync16(sb + 2 * TILEB + sdst, Bg);
        cpasync16(sb + 2 * TILEB + sdst + 16, Bg + 8);
        asm volatile("cp.async.commit_group;" ::: "memory");
    }

    for (int it = 0; it < niter; ++it) {
        if (it + 1 < niter) {
            const uint32_t bo = (uint32_t)((it + 1) & 1) * TILEB;
            const int ko = (it + 1) * 32;
            cpasync16(sb + bo + sdst, Ag + ko);
            cpasync16(sb + bo + sdst + 16, Ag + ko + 8);
            cpasync16(sb + 2 * TILEB + bo + sdst, Bg + ko);
            cpasync16(sb + 2 * TILEB + bo + sdst + 16, Bg + ko + 8);
            asm volatile("cp.async.commit_group;" ::: "memory");
            asm volatile("cp.async.wait_group 1;" ::: "memory");
        } else {
            asm volatile("cp.async.wait_group 0;" ::: "memory");
        }
        __syncthreads();

        const uint32_t sA = sb + (uint32_t)(it & 1) * TILEB;
        const uint32_t sB = sA + 2 * TILEB;
        #pragma unroll
        for (int ks = 0; ks < 2; ++ks) {
            uint32_t af[4][4], bf[4][2];
            #pragma unroll
            for (int mf = 0; mf < 4; ++mf)
                ldmx4(af[mf], sA + (uint32_t)(a_row + mf * 16) * LPB
                              + (uint32_t)(ks * 16 + a_col8) * 2);
            #pragma unroll
            for (int nf2 = 0; nf2 < 2; ++nf2) {
                uint32_t r[4];
                ldmx4(r, sB + (uint32_t)(b_row + nf2 * 16) * LPB
                         + (uint32_t)(ks * 16 + b_col8) * 2);
                bf[nf2 * 2][0] = r[0]; bf[nf2 * 2][1] = r[1];
                bf[nf2 * 2 + 1][0] = r[2]; bf[nf2 * 2 + 1][1] = r[3];
            }
            #pragma unroll
            for (int mf = 0; mf < 4; ++mf)
                #pragma unroll
                for (int nf = 0; nf < 4; ++nf)
                    mma16816(acc[mf][nf], af[mf], bf[nf]);
        }
        __syncthreads();
    }

    const int erow = lane >> 2, ecol = (lane & 3) * 2;
    #pragma unroll
    for (int mf = 0; mf < 4; ++mf) {
        #pragma unroll
        for (int nf = 0; nf < 4; ++nf) {
            const int col = wn + nf * 8 + ecol;
            float b0v = bias ? bias[n0 + col] : 0.f;
            float b1v = bias ? bias[n0 + col + 1] : 0.f;
            float v00 = acc[mf][nf][0] + b0v, v01 = acc[mf][nf][1] + b1v;
            float v10 = acc[mf][nf][2] + b0v, v11 = acc[mf][nf][3] + b1v;
            const size_t r0 = (size_t)(m0 + wm + mf * 16 + erow);
            if (Cb) {
                __nv_bfloat162 p0 = __float22bfloat162_rn(make_float2(v00, v01));
                __nv_bfloat162 p1 = __float22bfloat162_rn(make_float2(v10, v11));
                *(uint32_t*)(Cb + r0 * ldc + n0 + col) = *(uint32_t*)&p0;
                *(uint32_t*)(Cb + (r0 + 8) * ldc + n0 + col) = *(uint32_t*)&p1;
            } else {
                *(float2*)(Cf + r0 * ldc + n0 + col) = make_float2(v00, v01);
                *(float2*)(Cf + (r0 + 8) * ldc + n0 + col) = make_float2(v10, v11);
            }
        }
    }
}

// ------------------------- persistent skewed RNN ---------------------------
__global__ __launch_bounds__(256, 1) void rnn_kernel(const float* __restrict__ Wh,
                                                     const float* __restrict__ pre0) {
    extern __shared__ float sm[];
    float* Wsh = sm;
    float* red = sm + 24 * WPAD;
    const int tid = threadIdx.x;
    const int r0 = blockIdx.x * 8;

    for (int idx = tid; idx < 24 * 256; idx += 256) {
        int j = idx >> 8, c = (idx & 255) * 4;
        const float* srow;
        if (j < 8)       srow = Wh + (size_t)(r0 + j) * H;
        else if (j < 16) srow = g_M10 + (size_t)(r0 + j - 8) * H;
        else             srow = Wh + (size_t)H * H + (size_t)(r0 + j - 16) * H;
        *(float4*)(Wsh + j * WPAD + c) = __ldg((const float4*)(srow + c));
    }
    {
        int t = tid;
        int layer = t >> 7, slot = (t >> 6) & 1, b = (t >> 3) & 7, rr = t & 7;
        float* buf = layer ? g_h1buf : g_h0buf;
        buf[slot * (BB * H) + b * H + r0 + rr] = 0.f;
    }
    grid_barrier();

    const int lane = tid & 31, w = tid >> 5;
    const int rl = lane >> 2, bp = (lane & 3) * 2;
    const float* w0p = Wsh + rl * WPAD + w * 128;
    const float* w1p = Wsh + (8 + rl) * WPAD + w * 128;
    const float* w2p = Wsh + (16 + rl) * WPAD + w * 128;
    const int hoffA = bp * H + w * 128;
    const int hoffB = hoffA + H;
    const int ridx = w * 64 + rl * 8 + bp;

    for (int tick = 0; tick <= SS; ++tick) {
        const float* h0 = g_h0buf + (((tick & 1) ^ 1)) * (BB * H);
        const float* h1 = g_h1buf + ((tick & 1)) * (BB * H);
        const bool doA = (tick < SS), doB = (tick >= 1);

        ull m0a0 = 0, m0a1 = 0, m0b0 = 0, m0b1 = 0;
        ull m1a0 = 0, m1a1 = 0, m1b0 = 0, m1b1 = 0;
        ull m2a0 = 0, m2a1 = 0, m2b0 = 0, m2b1 = 0;

        if (doA && doB) {
            #pragma unroll 4
            for (int i = 0; i < 32; ++i) {
                ulonglong2 w0 = *(const ulonglong2*)(w0p + i * 4);
                ulonglong2 w1 = *(const ulonglong2*)(w1p + i * 4);
                ulonglong2 w2 = *(const ulonglong2*)(w2p + i * 4);
                ulonglong2 h0a = ldcg2(h0 + hoffA + i * 4);
                ulonglong2 h0b = ldcg2(h0 + hoffB + i * 4);
                ulonglong2 h1a = ldcg2(h1 + hoffA + i * 4);
                ulonglong2 h1b = ldcg2(h1 + hoffB + i * 4);
                m0a0 = ffma2(w0.x, h0a.x, m0a0); m0a1 = ffma2(w0.y, h0a.y, m0a1);
                m0b0 = ffma2(w0.x, h0b.x, m0b0); m0b1 = ffma2(w0.y, h0b.y, m0b1);
                m1a0 = ffma2(w1.x, h0a.x, m1a0); m1a1 = ffma2(w1.y, h0a.y, m1a1);
                m1b0 = ffma2(w1.x, h0b.x, m1b0); m1b1 = ffma2(w1.y, h0b.y, m1b1);
                m2a0 = ffma2(w2.x, h1a.x, m2a0); m2a1 = ffma2(w2.y, h1a.y, m2a1);
                m2b0 = ffma2(w2.x, h1b.x, m2b0); m2b1 = ffma2(w2.y, h1b.y, m2b1);
            }
        } else if (doA) {
            #pragma unroll 4
            for (int i = 0; i < 32; ++i) {
                ulonglong2 w0 = *(const ulonglong2*)(w0p + i * 4);
                ulonglong2 h0a = ldcg2(h0 + hoffA + i * 4);
                ulonglong2 h0b = ldcg2(h0 + hoffB + i * 4);
                m0a0 = ffma2(w0.x, h0a.x, m0a0); m0a1 = ffma2(w0.y, h0a.y, m0a1);
                m0b0 = ffma2(w0.x, h0b.x, m0b0); m0b1 = ffma2(w0.y, h0b.y, m0b1);
            }
        } else {
            #pragma unroll 4
            for (int i = 0; i < 32; ++i) {
                ulonglong2 w1 = *(const ulonglong2*)(w1p + i * 4);
                ulonglong2 w2 = *(const ulonglong2*)(w2p + i * 4);
                ulonglong2 h0a = ldcg2(h0 + hoffA + i * 4);
                ulonglong2 h0b = ldcg2(h0 + hoffB + i * 4);
                ulonglong2 h1a = ldcg2(h1 + hoffA + i * 4);
                ulonglong2 h1b = ldcg2(h1 + hoffB + i * 4);
                m1a0 = ffma2(w1.x, h0a.x, m1a0); m1a1 = ffma2(w1.y, h0a.y, m1a1);
                m1b0 = ffma2(w1.x, h0b.x, m1b0); m1b1 = ffma2(w1.y, h0b.y, m1b1);
                m2a0 = ffma2(w2.x, h1a.x, m2a0); m2a1 = ffma2(w2.y, h1a.y, m2a1);
                m2b0 = ffma2(w2.x, h1b.x, m2b0); m2b1 = ffma2(w2.y, h1b.y, m2b1);
            }
        }

        if (doA) {
            red[ridx]     = hsum4(m0a0, m0a1);
            red[ridx + 1] = hsum4(m0b0, m0b1);
        }
        if (doB) {
            red[512 + ridx]      = hsum4(m1a0, m1a1);
            red[512 + ridx + 1]  = hsum4(m1b0, m1b1);
            red[1024 + ridx]     = hsum4(m2a0, m2a1);
            red[1024 + ridx + 1] = hsum4(m2b0, m2b1);
        }
        __syncthreads();

        if (tid < 64) {
            if (doA) {
                int r = tid >> 3, b = tid & 7;
                float s = 0.f;
                #pragma unroll
                for (int ww = 0; ww < 8; ++ww) s += red[ww * 64 + tid];
                float v = tanhf(pre0[(size_t)(b * SS + tick) * H + r0 + r] + s);
                __stcg(&g_h0buf[(tick & 1) * (BB * H) + b * H + r0 + r], v);
            }
        } else if (tid < 128) {
            if (doB) {
                int j = tid - 64;
                int r = j >> 3, b = j & 7;
                float s1 = 0.f, s2 = 0.f;
                #pragma unroll
                for (int ww = 0; ww < 8; ++ww) {
                    s1 += red[512 + ww * 64 + j];
                    s2 += red[1024 + ww * 64 + j];
                }
                float v = tanhf(g_c1[r0 + r] + s1 + s2);
                __stcg(&g_h1buf[((tick & 1) ^ 1) * (BB * H) + b * H + r0 + r], v);
                g_HS1b[(size_t)(b * SS + tick - 1) * H + r0 + r] = __float2bfloat16(v);
            }
        }
        grid_barrier();
    }
}

// ------------------------- softmax (no-max, FMA-pipe exp) ------------------
__global__ __launch_bounds__(256) void softmax_kernel(float* __restrict__ logits) {
    extern __shared__ float sh[];
    float* row = sh;
    float* red = sh + VV;
    const int tid = threadIdx.x;
    float4* src = (float4*)(logits + (size_t)blockIdx.x * VV);

    float s = 0.f;
    for (int i = tid; i < VV / 4; i += 256) {
        float4 v = src[i];
        float4 e;
        e.x = fexp(v.x); e.y = fexp(v.y); e.z = fexp(v.z); e.w = fexp(v.w);
        ((float4*)row)[i] = e;
        s += (e.x + e.y) + (e.z + e.w);
    }
    #pragma unroll
    for (int o = 16; o; o >>= 1) s += __shfl_xor_sync(0xffffffffu, s, o);
    if ((tid & 31) == 0) red[tid >> 5] = s;
    __syncthreads();
    if (tid == 0) {
        float t = 0.f;
        for (int i = 0; i < 8; i++) t += red[i];
        red[32] = 1.0f / t;
    }
    __syncthreads();
    float inv = red[32];

    for (int i = tid; i < VV / 4; i += 256) {
        float4 v = ((float4*)row)[i];
        v.x *= inv; v.y *= inv; v.z *= inv; v.w *= inv;
        src[i] = v;
    }
}

// ------------------------- launch ------------------------------------------
extern "C" void kernel_launch(void* const* d_in, const int* in_sizes, int n_in,
                              void* d_out, int out_size) {
    const int*   tokens = (const int*)d_in[0];
    const float* E  = (const float*)d_in[1];
    const float* Wi = (const float*)d_in[2];
    const float* bi = (const float*)d_in[3];
    const float* Wh = (const float*)d_in[4];
    const float* bh = (const float*)d_in[5];
    const float* Wo = (const float*)d_in[6];
    const float* bo = (const float*)d_in[7];
    float* out = (float*)d_out;

    cudaFuncSetAttribute(rnn_kernel, cudaFuncAttributeMaxDynamicSharedMemorySize, RNN_SMEM);
    cudaFuncSetAttribute(softmax_kernel, cudaFuncAttributeMaxDynamicSharedMemorySize, SMAX_SMEM);

    static float *pPre0 = nullptr, *pM10, *pB0;
    static __nv_bfloat16 *pEb, *pXb, *pWib, *pWo0Tb, *pWo1b, *pHS1b, *pYb;
    if (!pPre0) {
        cudaGetSymbolAddress((void**)&pPre0,  g_pre0);
        cudaGetSymbolAddress((void**)&pM10,   g_M10);
        cudaGetSymbolAddress((void**)&pB0,    g_b0);
        cudaGetSymbolAddress((void**)&pEb,    g_Eb);
        cudaGetSymbolAddress((void**)&pXb,    g_Xb);
        cudaGetSymbolAddress((void**)&pWib,   g_Wib);
        cudaGetSymbolAddress((void**)&pWo0Tb, g_Wo0Tb);
        cudaGetSymbolAddress((void**)&pWo1b,  g_Wo1b);
        cudaGetSymbolAddress((void**)&pHS1b,  g_HS1b);
        cudaGetSymbolAddress((void**)&pYb,    g_Yb);
    }

    gather_kernel<<<MALL, 256>>>(tokens, E);                      // -> g_Xb (bf16)
    transpose_kernel<<<dim3(32, 32), dim3(32, 8)>>>(Wo);          // -> g_Wo0Tb
    prep_kernel<<<128, 256>>>(Wi, bi, bh, bo);                    // -> g_c1, g_b0
    conv_bf16<<<(VV * H / 8 + 255) / 256, 256>>>(E, pEb, VV * H / 8);
    conv_bf16<<<(2 * H * H / 8 + 255) / 256, 256>>>(Wi, pWib, 2 * H * H / 8);
    conv_bf16<<<(H * H / 8 + 255) / 256, 256>>>(Wo + (size_t)H * H, pWo1b, H * H / 8);
    // pre0 = X @ Wi0.T + (bi0+bh0)                    [fp32 out]
    gemm_bf16_mma<<<dim3(16, 8), 256>>>(pXb, pWib, pB0, pPre0, nullptr, H, H);
    // M10 = Wi1 @ Wo0                                 [fp32 out]
    gemm_bf16_mma<<<dim3(8, 8), 256>>>(pWib + (size_t)H * H, pWo0Tb, nullptr, pM10, nullptr, H, H);
    // recurrence -> g_HS1b (bf16)
    rnn_kernel<<<NB_RNN, 256, RNN_SMEM>>>(Wh, pPre0);
    // Yb = HS1 @ Wo1.T + bo1                          [bf16 out]
    gemm_bf16_mma<<<dim3(16, 8), 256>>>(pHS1b, pWo1b, bo + H, nullptr, pYb, H, H);
    // logits = Y @ E.T                                [fp32 out]
    gemm_bf16_mma<<<dim3(16, VV / 128), 256>>>(pYb, pEb, nullptr, out, nullptr, H, VV);
    // softmax in place
    softmax_kernel<<<MALL, 256, SMAX_SMEM>>>(out);
}

// round 6
// speedup vs baseline: 1.6848x; 1.0120x over previous
#include <cuda_runtime.h>
#include <cuda_bf16.h>
#include <cstddef>
#include <cstdint>

typedef unsigned long long ull;

#define H    1024
#define BB   8
#define SS   256
#define VV   32000
#define MALL (BB*SS)          // 2048
#define NB_RNN 128
#define WPAD 1028
#define RNN_SMEM  122880      // forces 1 CTA/SM (co-residency for grid barrier)
#define SMAX_SMEM ((VV + 64) * 4)

// ------------------------- device scratch ----------------------------------
__device__ float g_pre0[MALL * H];
__device__ float g_M10[H * H];
__device__ float g_c1[H];
__device__ float g_b0[H];
__device__ float g_h0buf[2 * BB * H];
__device__ float g_h1buf[2 * BB * H];
__device__ __nv_bfloat16 g_Eb[(size_t)VV * H];    // 64MB
__device__ __nv_bfloat16 g_Xb[MALL * H];          // 4MB
__device__ __nv_bfloat16 g_Wib[2 * H * H];        // 4MB
__device__ __nv_bfloat16 g_Wo0Tb[H * H];          // 2MB
__device__ __nv_bfloat16 g_Wo1b[H * H];           // 2MB
__device__ __nv_bfloat16 g_HS1b[MALL * H];        // 4MB
__device__ __nv_bfloat16 g_Yb[MALL * H];          // 4MB
__device__ volatile unsigned g_bar_gen;
__device__ unsigned g_bar_cnt;

// ------------------------- f32x2 helpers (RNN path) ------------------------
__device__ __forceinline__ ull ffma2(ull a, ull b, ull c) {
    ull d;
    asm("fma.rn.f32x2 %0, %1, %2, %3;" : "=l"(d) : "l"(a), "l"(b), "l"(c));
    return d;
}
__device__ __forceinline__ float2 unpack2(ull v) {
    float x, y;
    asm("mov.b64 {%0, %1}, %2;" : "=f"(x), "=f"(y) : "l"(v));
    return make_float2(x, y);
}
__device__ __forceinline__ float hsum4(ull a, ull b) {
    float2 x = unpack2(a), y = unpack2(b);
    return (x.x + x.y) + (y.x + y.y);
}
__device__ __forceinline__ ulonglong2 ldcg2(const float* p) {
    ulonglong2 r;
    asm volatile("ld.global.cg.v2.u64 {%0,%1}, [%2];"
                 : "=l"(r.x), "=l"(r.y) : "l"(p));
    return r;
}
__device__ __forceinline__ uint32_t smem_u32(const void* p) {
    uint32_t a;
    asm("{ .reg .u64 t; cvta.to.shared.u64 t, %1; cvt.u32.u64 %0, t; }"
        : "=r"(a) : "l"(p));
    return a;
}
__device__ __forceinline__ void cpasync16(uint32_t dst, const void* src) {
    asm volatile("cp.async.cg.shared.global [%0], [%1], 16;"
                 :: "r"(dst), "l"(src));
}
__device__ __forceinline__ void ldmx4(uint32_t* r, uint32_t addr) {
    asm volatile("ldmatrix.sync.aligned.m8n8.x4.shared.b16 {%0,%1,%2,%3}, [%4];"
                 : "=r"(r[0]), "=r"(r[1]), "=r"(r[2]), "=r"(r[3]) : "r"(addr));
}
__device__ __forceinline__ void mma16816(float* d, const uint32_t* a, const uint32_t* b) {
    asm volatile(
        "mma.sync.aligned.m16n8k16.row.col.f32.bf16.bf16.f32 "
        "{%0,%1,%2,%3}, {%4,%5,%6,%7}, {%8,%9}, {%0,%1,%2,%3};"
        : "+f"(d[0]), "+f"(d[1]), "+f"(d[2]), "+f"(d[3])
        : "r"(a[0]), "r"(a[1]), "r"(a[2]), "r"(a[3]), "r"(b[0]), "r"(b[1]));
}

// fast exp on the fma/alu pipes (valid for |x| < ~80; err ~4e-5 rel)
__device__ __forceinline__ float fexp(float x) {
    float km = fmaf(x, 1.4426950408889634f, 12582912.0f);
    int   ik = __float_as_int(km) - 0x4B400000;
    float kf = km - 12582912.0f;
    float f  = fmaf(kf, -0.6931471805599453f, x);
    float p  = fmaf(f, 0.041666668f, 0.16666667f);
    p = fmaf(p, f, 0.5f);
    p = fmaf(p, f, 1.0f);
    p = fmaf(p, f, 1.0f);
    return __int_as_float(__float_as_int(p) + (ik << 23));
}

// ------------------------- grid barrier ------------------------------------
__device__ __forceinline__ void grid_barrier() {
    __threadfence();
    __syncthreads();
    if (threadIdx.x == 0) {
        unsigned my = g_bar_gen;
        unsigned t = atomicAdd(&g_bar_cnt, 1u);
        if (t == NB_RNN - 1u) {
            g_bar_cnt = 0u;
            __threadfence();
            g_bar_gen = my + 1u;
        } else {
            while (g_bar_gen == my) { __nanosleep(64); }
        }
        __threadfence();
    }
    __syncthreads();
}

// ------------------------- embedding gather (emit bf16) --------------------
__global__ __launch_bounds__(256) void gather_kernel(const int* __restrict__ tokens,
                                                     const float* __restrict__ E) {
    int m = blockIdx.x;
    int b = m >> 8, t = m & 255;
    int tok = tokens[b * SS + t];
    float4 v = __ldg((const float4*)(E + (size_t)tok * H) + threadIdx.x);
    __nv_bfloat162 lo = __float22bfloat162_rn(make_float2(v.x, v.y));
    __nv_bfloat162 hi = __float22bfloat162_rn(make_float2(v.z, v.w));
    uint2 u;
    u.x = *(uint32_t*)&lo; u.y = *(uint32_t*)&hi;
    ((uint2*)(g_Xb + (size_t)m * H))[threadIdx.x] = u;
}

// ------------------------- Wo0 transpose -> bf16 ---------------------------
__global__ void transpose_kernel(const float* __restrict__ in) {
    __shared__ float t[32][33];
    int bx = blockIdx.x * 32, by = blockIdx.y * 32;
    int tx = threadIdx.x;
    for (int j = threadIdx.y; j < 32; j += 8)
        t[j][tx] = in[(size_t)(by + j) * H + bx + tx];
    __syncthreads();
    for (int j = threadIdx.y; j < 32; j += 8)
        g_Wo0Tb[(size_t)(bx + j) * H + by + tx] = __float2bfloat16(t[tx][j]);
}

// ------------------------- bias prep ---------------------------------------
__global__ __launch_bounds__(256) void prep_kernel(const float* __restrict__ Wi,
                                                   const float* __restrict__ bi,
                                                   const float* __restrict__ bh,
                                                   const float* __restrict__ bo) {
    int w = threadIdx.x >> 5, lane = threadIdx.x & 31;
    int r = blockIdx.x * 8 + w;
    const float* Wi1r = Wi + (size_t)H * H + (size_t)r * H;
    float s = 0.f;
    for (int k = lane; k < H; k += 32) s += Wi1r[k] * bo[k];
    #pragma unroll
    for (int off = 16; off; off >>= 1) s += __shfl_xor_sync(0xffffffffu, s, off);
    if (lane == 0) {
        g_c1[r] = s + bi[H + r] + bh[H + r];
        g_b0[r] = bi[r] + bh[r];
    }
}

// ------------------------- fp32 -> bf16 convert ----------------------------
__global__ __launch_bounds__(256) void conv_bf16(const float* __restrict__ in,
                                                 __nv_bfloat16* __restrict__ out,
                                                 int n8) {
    int i = blockIdx.x * 256 + threadIdx.x;
    if (i >= n8) return;
    const float4* p = (const float4*)in + (size_t)i * 2;
    float4 a = __ldg(p), b = __ldg(p + 1);
    __nv_bfloat162 r0 = __float22bfloat162_rn(make_float2(a.x, a.y));
    __nv_bfloat162 r1 = __float22bfloat162_rn(make_float2(a.z, a.w));
    __nv_bfloat162 r2 = __float22bfloat162_rn(make_float2(b.x, b.y));
    __nv_bfloat162 r3 = __float22bfloat162_rn(make_float2(b.z, b.w));
    uint4 u;
    u.x = *(uint32_t*)&r0; u.y = *(uint32_t*)&r1;
    u.z = *(uint32_t*)&r2; u.w = *(uint32_t*)&r3;
    ((uint4*)out)[i] = u;
}

// ------------------------- bf16 mma.sync NT GEMM, 128x256 tile, 4 stages ---
// C[m][n] = bias[n] + sum_k A[m*K+k]*B[n*K+k]; M mult 128, N mult 256, K mult 32.
// 8 warps as 2(m) x 4(n); warp tile 64x64. SMEM: 4 stages x (A 128x40 + B 256x40) bf16.
#define LPB     80                        // bytes per padded row (32 bf16 + 8 pad)
#define ASTG    (128 * LPB)               // 10240
#define BSTG    (256 * LPB)               // 20480
#define STG     (ASTG + BSTG)             // 30720
#define GM_SMEM (4 * STG)                 // 122880
__global__ __launch_bounds__(256, 1) void gemm_bf16_mma(
    const __nv_bfloat16* __restrict__ A,
    const __nv_bfloat16* __restrict__ B,
    const float* __restrict__ bias,
    float* __restrict__ Cf,
    __nv_bfloat16* __restrict__ Cb,
    int K, int ldc)
{
    extern __shared__ __align__(16) char smem[];
    const uint32_t sb = smem_u32(smem);
    const int tid = threadIdx.x;
    const int m0 = blockIdx.x * 128, n0 = blockIdx.y * 256;
    const int niter = K >> 5;

    // loader: A 512 16B-chunks (2/thread), B 1024 (4/thread)
    const int arow0 = tid >> 1;                 // chunks tid*2, tid*2+1 -> row tid>>1? no:
    // chunk c: row = c>>2, col8 = (c&3)*8 elems. Use c = tid and c+256 for A; c=tid+256*j for B.
    float acc[4][8][4];
    #pragma unroll
    for (int i = 0; i < 4; i++)
        #pragma unroll
        for (int j = 0; j < 8; j++)
            #pragma unroll
            for (int q = 0; q < 4; q++) acc[i][j][q] = 0.f;

    const int w = tid >> 5, lane = tid & 31;
    const int wm = (w >> 2) * 64, wn = (w & 3) * 64;
    const int a_row = wm + ((lane >> 3) & 1) * 8 + (lane & 7);
    const int a_col8 = ((lane >> 4) & 1) * 8;
    const int b_row = ((lane >> 4) & 1) * 8 + (lane & 7);   // + wn + nf2*16
    const int b_col8 = ((lane >> 3) & 1) * 8;

    auto issue_stage = [&](int s, int ko) {
        const uint32_t sA = sb + (uint32_t)s * STG;
        const uint32_t sB = sA + ASTG;
        #pragma unroll
        for (int j = 0; j < 2; ++j) {
            int c = tid + 256 * j;
            int row = c >> 2, col = (c & 3) * 8;
            cpasync16(sA + (uint32_t)row * LPB + (uint32_t)(c & 3) * 16,
                      A + (size_t)(m0 + row) * K + ko + col);
        }
        #pragma unroll
        for (int j = 0; j < 4; ++j) {
            int c = tid + 256 * j;
            int row = c >> 2, col = (c & 3) * 8;
            cpasync16(sB + (uint32_t)row * LPB + (uint32_t)(c & 3) * 16,
                      B + (size_t)(n0 + row) * K + ko + col);
        }
    };

    // prologue: stages 0..2
    #pragma unroll
    for (int s = 0; s < 3; ++s) {
        issue_stage(s, s * 32);
        asm volatile("cp.async.commit_group;" ::: "memory");
    }

    for (int it = 0; it < niter; ++it) {
        asm volatile("cp.async.wait_group 2;" ::: "memory");
        __syncthreads();
        if (it + 3 < niter) issue_stage((it + 3) & 3, (it + 3) * 32);
        asm volatile("cp.async.commit_group;" ::: "memory");

        const uint32_t sA = sb + (uint32_t)(it & 3) * STG;
        const uint32_t sB = sA + ASTG;
        #pragma unroll
        for (int ks = 0; ks < 2; ++ks) {
            uint32_t af[4][4], bf[8][2];
            #pragma unroll
            for (int mf = 0; mf < 4; ++mf)
                ldmx4(af[mf], sA + (uint32_t)(a_row + mf * 16) * LPB
                              + (uint32_t)(ks * 16 + a_col8) * 2);
            #pragma unroll
            for (int nf2 = 0; nf2 < 4; ++nf2) {
                uint32_t r[4];
                ldmx4(r, sB + (uint32_t)(wn + nf2 * 16 + b_row) * LPB
                         + (uint32_t)(ks * 16 + b_col8) * 2);
                bf[nf2 * 2][0] = r[0]; bf[nf2 * 2][1] = r[1];
                bf[nf2 * 2 + 1][0] = r[2]; bf[nf2 * 2 + 1][1] = r[3];
            }
            #pragma unroll
            for (int mf = 0; mf < 4; ++mf)
                #pragma unroll
                for (int nf = 0; nf < 8; ++nf)
                    mma16816(acc[mf][nf], af[mf], bf[nf]);
        }
    }

    const int erow = lane >> 2, ecol = (lane & 3) * 2;
    #pragma unroll
    for (int mf = 0; mf < 4; ++mf) {
        #pragma unroll
        for (int nf = 0; nf < 8; ++nf) {
            const int col = wn + nf * 8 + ecol;
            float b0v = bias ? bias[n0 + col] : 0.f;
            float b1v = bias ? bias[n0 + col + 1] : 0.f;
            float v00 = acc[mf][nf][0] + b0v, v01 = acc[mf][nf][1] + b1v;
            float v10 = acc[mf][nf][2] + b0v, v11 = acc[mf][nf][3] + b1v;
            const size_t r0 = (size_t)(m0 + wm + mf * 16 + erow);
            if (Cb) {
                __nv_bfloat162 p0 = __float22bfloat162_rn(make_float2(v00, v01));
                __nv_bfloat162 p1 = __float22bfloat162_rn(make_float2(v10, v11));
                *(uint32_t*)(Cb + r0 * ldc + n0 + col) = *(uint32_t*)&p0;
                *(uint32_t*)(Cb + (r0 + 8) * ldc + n0 + col) = *(uint32_t*)&p1;
            } else {
                *(float2*)(Cf + r0 * ldc + n0 + col) = make_float2(v00, v01);
                *(float2*)(Cf + (r0 + 8) * ldc + n0 + col) = make_float2(v10, v11);
            }
        }
    }
}

// ------------------------- persistent skewed RNN ---------------------------
__global__ __launch_bounds__(256, 1) void rnn_kernel(const float* __restrict__ Wh,
                                                     const float* __restrict__ pre0) {
    extern __shared__ float sm[];
    float* Wsh = sm;
    float* red = sm + 24 * WPAD;
    const int tid = threadIdx.x;
    const int r0 = blockIdx.x * 8;

    for (int idx = tid; idx < 24 * 256; idx += 256) {
        int j = idx >> 8, c = (idx & 255) * 4;
        const float* srow;
        if (j < 8)       srow = Wh + (size_t)(r0 + j) * H;
        else if (j < 16) srow = g_M10 + (size_t)(r0 + j - 8) * H;
        else             srow = Wh + (size_t)H * H + (size_t)(r0 + j - 16) * H;
        *(float4*)(Wsh + j * WPAD + c) = __ldg((const float4*)(srow + c));
    }
    {
        int t = tid;
        int layer = t >> 7, slot = (t >> 6) & 1, b = (t >> 3) & 7, rr = t & 7;
        float* buf = layer ? g_h1buf : g_h0buf;
        buf[slot * (BB * H) + b * H + r0 + rr] = 0.f;
    }
    grid_barrier();

    const int lane = tid & 31, w = tid >> 5;
    const int rl = lane >> 2, bp = (lane & 3) * 2;
    const float* w0p = Wsh + rl * WPAD + w * 128;
    const float* w1p = Wsh + (8 + rl) * WPAD + w * 128;
    const float* w2p = Wsh + (16 + rl) * WPAD + w * 128;
    const int hoffA = bp * H + w * 128;
    const int hoffB = hoffA + H;
    const int ridx = w * 64 + rl * 8 + bp;

    for (int tick = 0; tick <= SS; ++tick) {
        const float* h0 = g_h0buf + (((tick & 1) ^ 1)) * (BB * H);
        const float* h1 = g_h1buf + ((tick & 1)) * (BB * H);
        const bool doA = (tick < SS), doB = (tick >= 1);

        ull m0a0 = 0, m0a1 = 0, m0b0 = 0, m0b1 = 0;
        ull m1a0 = 0, m1a1 = 0, m1b0 = 0, m1b1 = 0;
        ull m2a0 = 0, m2a1 = 0, m2b0 = 0, m2b1 = 0;

        if (doA && doB) {
            #pragma unroll 4
            for (int i = 0; i < 32; ++i) {
                ulonglong2 w0 = *(const ulonglong2*)(w0p + i * 4);
                ulonglong2 w1 = *(const ulonglong2*)(w1p + i * 4);
                ulonglong2 w2 = *(const ulonglong2*)(w2p + i * 4);
                ulonglong2 h0a = ldcg2(h0 + hoffA + i * 4);
                ulonglong2 h0b = ldcg2(h0 + hoffB + i * 4);
                ulonglong2 h1a = ldcg2(h1 + hoffA + i * 4);
                ulonglong2 h1b = ldcg2(h1 + hoffB + i * 4);
                m0a0 = ffma2(w0.x, h0a.x, m0a0); m0a1 = ffma2(w0.y, h0a.y, m0a1);
                m0b0 = ffma2(w0.x, h0b.x, m0b0); m0b1 = ffma2(w0.y, h0b.y, m0b1);
                m1a0 = ffma2(w1.x, h0a.x, m1a0); m1a1 = ffma2(w1.y, h0a.y, m1a1);
                m1b0 = ffma2(w1.x, h0b.x, m1b0); m1b1 = ffma2(w1.y, h0b.y, m1b1);
                m2a0 = ffma2(w2.x, h1a.x, m2a0); m2a1 = ffma2(w2.y, h1a.y, m2a1);
                m2b0 = ffma2(w2.x, h1b.x, m2b0); m2b1 = ffma2(w2.y, h1b.y, m2b1);
            }
        } else if (doA) {
            #pragma unroll 4
            for (int i = 0; i < 32; ++i) {
                ulonglong2 w0 = *(const ulonglong2*)(w0p + i * 4);
                ulonglong2 h0a = ldcg2(h0 + hoffA + i * 4);
                ulonglong2 h0b = ldcg2(h0 + hoffB + i * 4);
                m0a0 = ffma2(w0.x, h0a.x, m0a0); m0a1 = ffma2(w0.y, h0a.y, m0a1);
                m0b0 = ffma2(w0.x, h0b.x, m0b0); m0b1 = ffma2(w0.y, h0b.y, m0b1);
            }
        } else {
            #pragma unroll 4
            for (int i = 0; i < 32; ++i) {
                ulonglong2 w1 = *(const ulonglong2*)(w1p + i * 4);
                ulonglong2 w2 = *(const ulonglong2*)(w2p + i * 4);
                ulonglong2 h0a = ldcg2(h0 + hoffA + i * 4);
                ulonglong2 h0b = ldcg2(h0 + hoffB + i * 4);
                ulonglong2 h1a = ldcg2(h1 + hoffA + i * 4);
                ulonglong2 h1b = ldcg2(h1 + hoffB + i * 4);
                m1a0 = ffma2(w1.x, h0a.x, m1a0); m1a1 = ffma2(w1.y, h0a.y, m1a1);
                m1b0 = ffma2(w1.x, h0b.x, m1b0); m1b1 = ffma2(w1.y, h0b.y, m1b1);
                m2a0 = ffma2(w2.x, h1a.x, m2a0); m2a1 = ffma2(w2.y, h1a.y, m2a1);
                m2b0 = ffma2(w2.x, h1b.x, m2b0); m2b1 = ffma2(w2.y, h1b.y, m2b1);
            }
        }

        if (doA) {
            red[ridx]     = hsum4(m0a0, m0a1);
            red[ridx + 1] = hsum4(m0b0, m0b1);
        }
        if (doB) {
            red[512 + ridx]      = hsum4(m1a0, m1a1);
            red[512 + ridx + 1]  = hsum4(m1b0, m1b1);
            red[1024 + ridx]     = hsum4(m2a0, m2a1);
            red[1024 + ridx + 1] = hsum4(m2b0, m2b1);
        }
        __syncthreads();

        if (tid < 64) {
            if (doA) {
                int r = tid >> 3, b = tid & 7;
                float s = 0.f;
                #pragma unroll
                for (int ww = 0; ww < 8; ++ww) s += red[ww * 64 + tid];
                float v = tanhf(pre0[(size_t)(b * SS + tick) * H + r0 + r] + s);
                __stcg(&g_h0buf[(tick & 1) * (BB * H) + b * H + r0 + r], v);
            }
        } else if (tid < 128) {
            if (doB) {
                int j = tid - 64;
                int r = j >> 3, b = j & 7;
                float s1 = 0.f, s2 = 0.f;
                #pragma unroll
                for (int ww = 0; ww < 8; ++ww) {
                    s1 += red[512 + ww * 64 + j];
                    s2 += red[1024 + ww * 64 + j];
                }
                float v = tanhf(g_c1[r0 + r] + s1 + s2);
                __stcg(&g_h1buf[((tick & 1) ^ 1) * (BB * H) + b * H + r0 + r], v);
                g_HS1b[(size_t)(b * SS + tick - 1) * H + r0 + r] = __float2bfloat16(v);
            }
        }
        grid_barrier();
    }
}

// ------------------------- softmax (no-max, FMA-pipe exp) ------------------
__global__ __launch_bounds__(256) void softmax_kernel(float* __restrict__ logits) {
    extern __shared__ float sh[];
    float* row = sh;
    float* red = sh + VV;
    const int tid = threadIdx.x;
    float4* src = (float4*)(logits + (size_t)blockIdx.x * VV);

    float s = 0.f;
    for (int i = tid; i < VV / 4; i += 256) {
        float4 v = src[i];
        float4 e;
        e.x = fexp(v.x); e.y = fexp(v.y); e.z = fexp(v.z); e.w = fexp(v.w);
        ((float4*)row)[i] = e;
        s += (e.x + e.y) + (e.z + e.w);
    }
    #pragma unroll
    for (int o = 16; o; o >>= 1) s += __shfl_xor_sync(0xffffffffu, s, o);
    if ((tid & 31) == 0) red[tid >> 5] = s;
    __syncthreads();
    if (tid == 0) {
        float t = 0.f;
        for (int i = 0; i < 8; i++) t += red[i];
        red[32] = 1.0f / t;
    }
    __syncthreads();
    float inv = red[32];

    for (int i = tid; i < VV / 4; i += 256) {
        float4 v = ((float4*)row)[i];
        v.x *= inv; v.y *= inv; v.z *= inv; v.w *= inv;
        src[i] = v;
    }
}

// ------------------------- launch ------------------------------------------
extern "C" void kernel_launch(void* const* d_in, const int* in_sizes, int n_in,
                              void* d_out, int out_size) {
    const int*   tokens = (const int*)d_in[0];
    const float* E  = (const float*)d_in[1];
    const float* Wi = (const float*)d_in[2];
    const float* bi = (const float*)d_in[3];
    const float* Wh = (const float*)d_in[4];
    const float* bh = (const float*)d_in[5];
    const float* Wo = (const float*)d_in[6];
    const float* bo = (const float*)d_in[7];
    float* out = (float*)d_out;

    cudaFuncSetAttribute(rnn_kernel, cudaFuncAttributeMaxDynamicSharedMemorySize, RNN_SMEM);
    cudaFuncSetAttribute(softmax_kernel, cudaFuncAttributeMaxDynamicSharedMemorySize, SMAX_SMEM);
    cudaFuncSetAttribute(gemm_bf16_mma, cudaFuncAttributeMaxDynamicSharedMemorySize, GM_SMEM);

    static float *pPre0 = nullptr, *pM10, *pB0;
    static __nv_bfloat16 *pEb, *pXb, *pWib, *pWo0Tb, *pWo1b, *pHS1b, *pYb;
    if (!pPre0) {
        cudaGetSymbolAddress((void**)&pPre0,  g_pre0);
        cudaGetSymbolAddress((void**)&pM10,   g_M10);
        cudaGetSymbolAddress((void**)&pB0,    g_b0);
        cudaGetSymbolAddress((void**)&pEb,    g_Eb);
        cudaGetSymbolAddress((void**)&pXb,    g_Xb);
        cudaGetSymbolAddress((void**)&pWib,   g_Wib);
        cudaGetSymbolAddress((void**)&pWo0Tb, g_Wo0Tb);
        cudaGetSymbolAddress((void**)&pWo1b,  g_Wo1b);
        cudaGetSymbolAddress((void**)&pHS1b,  g_HS1b);
        cudaGetSymbolAddress((void**)&pYb,    g_Yb);
    }

    gather_kernel<<<MALL, 256>>>(tokens, E);
    transpose_kernel<<<dim3(32, 32), dim3(32, 8)>>>(Wo);
    prep_kernel<<<128, 256>>>(Wi, bi, bh, bo);
    conv_bf16<<<(VV * H / 8 + 255) / 256, 256>>>(E, pEb, VV * H / 8);
    conv_bf16<<<(2 * H * H / 8 + 255) / 256, 256>>>(Wi, pWib, 2 * H * H / 8);
    conv_bf16<<<(H * H / 8 + 255) / 256, 256>>>(Wo + (size_t)H * H, pWo1b, H * H / 8);
    // pre0 = X @ Wi0.T + (bi0+bh0)          [fp32 out]
    gemm_bf16_mma<<<dim3(16, 4), 256, GM_SMEM>>>(pXb, pWib, pB0, pPre0, nullptr, H, H);
    // M10 = Wi1 @ Wo0                       [fp32 out]
    gemm_bf16_mma<<<dim3(8, 4), 256, GM_SMEM>>>(pWib + (size_t)H * H, pWo0Tb, nullptr, pM10, nullptr, H, H);
    // recurrence -> g_HS1b (bf16)
    rnn_kernel<<<NB_RNN, 256, RNN_SMEM>>>(Wh, pPre0);
    // Yb = HS1 @ Wo1.T + bo1                [bf16 out]
    gemm_bf16_mma<<<dim3(16, 4), 256, GM_SMEM>>>(pHS1b, pWo1b, bo + H, nullptr, pYb, H, H);
    // logits = Y @ E.T                      [fp32 out]
    gemm_bf16_mma<<<dim3(16, VV / 256), 256, GM_SMEM>>>(pYb, pEb, nullptr, out, nullptr, H, VV);
    // softmax in place
    softmax_kernel<<<MALL, 256, SMAX_SMEM>>>(out);
}

// round 8
// speedup vs baseline: 2.8618x; 1.6986x over previous
#include <cuda_runtime.h>
#include <cuda_bf16.h>
#include <cstddef>
#include <cstdint>

typedef unsigned long long ull;

#define H    1024
#define BB   8
#define SS   256
#define VV   32000
#define MALL (BB*SS)          // 2048
#define NB_RNN 128
#define NTILE 125             // logits n-tiles (32000/256)
// RNN smem: W 24x1028 | hs0 8x1028 | hs1 8x1028 | red 8x192  (floats)
#define RNN_SMEM ((24*1028 + 16*1028 + 8*192) * 4)   // 170624

// ------------------------- device scratch ----------------------------------
__device__ float g_pre0[MALL * H];
__device__ float g_M10[H * H];
__device__ float g_c1[H];
__device__ float g_b0[H];
__device__ float g_h0buf[2 * BB * H];
__device__ float g_h1buf[2 * BB * H];
__device__ float g_psum[(size_t)MALL * NTILE];
__device__ __nv_bfloat16 g_Eb[(size_t)VV * H];    // 64MB
__device__ __nv_bfloat16 g_Xb[MALL * H];
__device__ __nv_bfloat16 g_Wib[2 * H * H];
__device__ __nv_bfloat16 g_Wo0Tb[H * H];
__device__ __nv_bfloat16 g_Wo1b[H * H];
__device__ __nv_bfloat16 g_HS1b[MALL * H];
__device__ __nv_bfloat16 g_Yb[MALL * H];
__device__ volatile unsigned g_bar_gen;
__device__ unsigned g_bar_cnt;

// ------------------------- helpers -----------------------------------------
__device__ __forceinline__ ull ffma2(ull a, ull b, ull c) {
    ull d;
    asm("fma.rn.f32x2 %0, %1, %2, %3;" : "=l"(d) : "l"(a), "l"(b), "l"(c));
    return d;
}
__device__ __forceinline__ float2 unpack2(ull v) {
    float x, y;
    asm("mov.b64 {%0, %1}, %2;" : "=f"(x), "=f"(y) : "l"(v));
    return make_float2(x, y);
}
__device__ __forceinline__ float hsum2(ull a) {
    float2 p = unpack2(a);
    return p.x + p.y;
}
__device__ __forceinline__ float4 ldcg4(const float* p) {
    float4 v;
    asm volatile("ld.global.cg.v4.f32 {%0,%1,%2,%3}, [%4];"
                 : "=f"(v.x), "=f"(v.y), "=f"(v.z), "=f"(v.w) : "l"(p));
    return v;
}
__device__ __forceinline__ uint32_t smem_u32(const void* p) {
    uint32_t a;
    asm("{ .reg .u64 t; cvta.to.shared.u64 t, %1; cvt.u32.u64 %0, t; }"
        : "=r"(a) : "l"(p));
    return a;
}
__device__ __forceinline__ void cpasync16(uint32_t dst, const void* src) {
    asm volatile("cp.async.cg.shared.global [%0], [%1], 16;"
                 :: "r"(dst), "l"(src));
}
__device__ __forceinline__ void ldmx4(uint32_t* r, uint32_t addr) {
    asm volatile("ldmatrix.sync.aligned.m8n8.x4.shared.b16 {%0,%1,%2,%3}, [%4];"
                 : "=r"(r[0]), "=r"(r[1]), "=r"(r[2]), "=r"(r[3]) : "r"(addr));
}
__device__ __forceinline__ void mma16816(float* d, const uint32_t* a, const uint32_t* b) {
    asm volatile(
        "mma.sync.aligned.m16n8k16.row.col.f32.bf16.bf16.f32 "
        "{%0,%1,%2,%3}, {%4,%5,%6,%7}, {%8,%9}, {%0,%1,%2,%3};"
        : "+f"(d[0]), "+f"(d[1]), "+f"(d[2]), "+f"(d[3])
        : "r"(a[0]), "r"(a[1]), "r"(a[2]), "r"(a[3]), "r"(b[0]), "r"(b[1]));
}
// fast exp on fma/alu pipes (|x| < ~80; rel err ~4e-5)
__device__ __forceinline__ float fexp(float x) {
    float km = fmaf(x, 1.4426950408889634f, 12582912.0f);
    int   ik = __float_as_int(km) - 0x4B400000;
    float kf = km - 12582912.0f;
    float f  = fmaf(kf, -0.6931471805599453f, x);
    float p  = fmaf(f, 0.041666668f, 0.16666667f);
    p = fmaf(p, f, 0.5f);
    p = fmaf(p, f, 1.0f);
    p = fmaf(p, f, 1.0f);
    return __int_as_float(__float_as_int(p) + (ik << 23));
}

// ------------------------- grid barrier ------------------------------------
__device__ __forceinline__ void grid_barrier() {
    __threadfence();
    __syncthreads();
    if (threadIdx.x == 0) {
        unsigned my = g_bar_gen;
        unsigned t = atomicAdd(&g_bar_cnt, 1u);
        if (t == NB_RNN - 1u) {
            g_bar_cnt = 0u;
            __threadfence();
            g_bar_gen = my + 1u;
        } else {
            while (g_bar_gen == my) { }
        }
        __threadfence();
    }
    __syncthreads();
}

// ------------------------- fused prep (launch #1) --------------------------
// blocks: [0,2048) gather | [2048,3072) transpose | [3072,3200) prep
//         [3200,4224) conv Wi | [4224,4736) conv Wo1
__global__ __launch_bounds__(256) void fused_prep(
    const int* __restrict__ tokens, const float* __restrict__ E,
    const float* __restrict__ Wi, const float* __restrict__ bi,
    const float* __restrict__ bh, const float* __restrict__ Wo,
    const float* __restrict__ bo)
{
    __shared__ float tbuf[32][33];
    const int bx = blockIdx.x, t = threadIdx.x;
    if (bx < 2048) {                       // gather -> g_Xb (bf16)
        int b = bx >> 8, tt = bx & 255;
        int tok = tokens[b * SS + tt];
        float4 v = __ldg((const float4*)(E + (size_t)tok * H) + t);
        __nv_bfloat162 lo = __float22bfloat162_rn(make_float2(v.x, v.y));
        __nv_bfloat162 hi = __float22bfloat162_rn(make_float2(v.z, v.w));
        uint2 u;
        u.x = *(uint32_t*)&lo; u.y = *(uint32_t*)&hi;
        ((uint2*)(g_Xb + (size_t)bx * H))[t] = u;
    } else if (bx < 3072) {                // Wo0 transpose -> g_Wo0Tb
        int id = bx - 2048;
        int bxt = (id & 31) * 32, byt = (id >> 5) * 32;
        int tx = t & 31, ty = t >> 5;
        for (int j = ty; j < 32; j += 8)
            tbuf[j][tx] = Wo[(size_t)(byt + j) * H + bxt + tx];
        __syncthreads();
        for (int j = ty; j < 32; j += 8)
            g_Wo0Tb[(size_t)(bxt + j) * H + byt + tx] = __float2bfloat16(tbuf[tx][j]);
    } else if (bx < 3200) {                // bias prep -> g_c1, g_b0
        int w = t >> 5, lane = t & 31;
        int r = (bx - 3072) * 8 + w;
        const float* Wi1r = Wi + (size_t)H * H + (size_t)r * H;
        float s = 0.f;
        for (int k = lane; k < H; k += 32) s += Wi1r[k] * bo[k];
        #pragma unroll
        for (int off = 16; off; off >>= 1) s += __shfl_xor_sync(0xffffffffu, s, off);
        if (lane == 0) {
            g_c1[r] = s + bi[H + r] + bh[H + r];
            g_b0[r] = bi[r] + bh[r];
        }
    } else if (bx < 4224) {                // conv Wi -> g_Wib
        int i = (bx - 3200) * 256 + t;
        const float4* p = (const float4*)Wi + (size_t)i * 2;
        float4 a = __ldg(p), b = __ldg(p + 1);
        __nv_bfloat162 r0 = __float22bfloat162_rn(make_float2(a.x, a.y));
        __nv_bfloat162 r1 = __float22bfloat162_rn(make_float2(a.z, a.w));
        __nv_bfloat162 r2 = __float22bfloat162_rn(make_float2(b.x, b.y));
        __nv_bfloat162 r3 = __float22bfloat162_rn(make_float2(b.z, b.w));
        uint4 u;
        u.x = *(uint32_t*)&r0; u.y = *(uint32_t*)&r1;
        u.z = *(uint32_t*)&r2; u.w = *(uint32_t*)&r3;
        ((uint4*)g_Wib)[i] = u;
    } else {                               // conv Wo1 -> g_Wo1b
        int i = (bx - 4224) * 256 + t;
        const float4* p = (const float4*)(Wo + (size_t)H * H) + (size_t)i * 2;
        float4 a = __ldg(p), b = __ldg(p + 1);
        __nv_bfloat162 r0 = __float22bfloat162_rn(make_float2(a.x, a.y));
        __nv_bfloat162 r1 = __float22bfloat162_rn(make_float2(a.z, a.w));
        __nv_bfloat162 r2 = __float22bfloat162_rn(make_float2(b.x, b.y));
        __nv_bfloat162 r3 = __float22bfloat162_rn(make_float2(b.z, b.w));
        uint4 u;
        u.x = *(uint32_t*)&r0; u.y = *(uint32_t*)&r1;
        u.z = *(uint32_t*)&r2; u.w = *(uint32_t*)&r3;
        ((uint4*)g_Wo1b)[i] = u;
    }
}

// ------------------------- fp32 -> bf16 convert (E) ------------------------
__global__ __launch_bounds__(256) void conv_bf16(const float* __restrict__ in,
                                                 __nv_bfloat16* __restrict__ out,
                                                 int n8) {
    int i = blockIdx.x * 256 + threadIdx.x;
    if (i >= n8) return;
    const float4* p = (const float4*)in + (size_t)i * 2;
    float4 a = __ldg(p), b = __ldg(p + 1);
    __nv_bfloat162 r0 = __float22bfloat162_rn(make_float2(a.x, a.y));
    __nv_bfloat162 r1 = __float22bfloat162_rn(make_float2(a.z, a.w));
    __nv_bfloat162 r2 = __float22bfloat162_rn(make_float2(b.x, b.y));
    __nv_bfloat162 r3 = __float22bfloat162_rn(make_float2(b.z, b.w));
    uint4 u;
    u.x = *(uint32_t*)&r0; u.y = *(uint32_t*)&r1;
    u.z = *(uint32_t*)&r2; u.w = *(uint32_t*)&r3;
    ((uint4*)out)[i] = u;
}

// ------------------------- bf16 mma.sync NT GEMM, 128x256 tile, 4 stages ---
// C[m][n] = bias[n] + sum_k A[m*K+k]*B[n*K+k]
// do_exp: epilogue stores fexp(C) and deterministic per-(row, n-CTA) sums.
#define LPB     80
#define ASTG    (128 * LPB)
#define BSTG    (256 * LPB)
#define STG     (ASTG + BSTG)
#define GM_SMEM (4 * STG)                 // 122880
__global__ __launch_bounds__(256, 1) void gemm_bf16_mma(
    const __nv_bfloat16* __restrict__ A,
    const __nv_bfloat16* __restrict__ B,
    const float* __restrict__ bias,
    float* __restrict__ Cf,
    __nv_bfloat16* __restrict__ Cb,
    int K, int ldc, int do_exp)
{
    extern __shared__ __align__(16) char smem[];
    __shared__ float sred[4][128];
    const uint32_t sb = smem_u32(smem);
    const int tid = threadIdx.x;
    const int m0 = blockIdx.x * 128, n0 = blockIdx.y * 256;
    const int niter = K >> 5;

    float acc[4][8][4];
    #pragma unroll
    for (int i = 0; i < 4; i++)
        #pragma unroll
        for (int j = 0; j < 8; j++)
            #pragma unroll
            for (int q = 0; q < 4; q++) acc[i][j][q] = 0.f;

    const int w = tid >> 5, lane = tid & 31;
    const int wm = (w >> 2) * 64, wn = (w & 3) * 64;
    const int a_row = wm + ((lane >> 3) & 1) * 8 + (lane & 7);
    const int a_col8 = ((lane >> 4) & 1) * 8;
    const int b_row = ((lane >> 4) & 1) * 8 + (lane & 7);
    const int b_col8 = ((lane >> 3) & 1) * 8;

    auto issue_stage = [&](int s, int ko) {
        const uint32_t sA = sb + (uint32_t)s * STG;
        const uint32_t sB = sA + ASTG;
        #pragma unroll
        for (int j = 0; j < 2; ++j) {
            int c = tid + 256 * j;
            int row = c >> 2, col = (c & 3) * 8;
            cpasync16(sA + (uint32_t)row * LPB + (uint32_t)(c & 3) * 16,
                      A + (size_t)(m0 + row) * K + ko + col);
        }
        #pragma unroll
        for (int j = 0; j < 4; ++j) {
            int c = tid + 256 * j;
            int row = c >> 2, col = (c & 3) * 8;
            cpasync16(sB + (uint32_t)row * LPB + (uint32_t)(c & 3) * 16,
                      B + (size_t)(n0 + row) * K + ko + col);
        }
    };

    #pragma unroll
    for (int s = 0; s < 3; ++s) {
        issue_stage(s, s * 32);
        asm volatile("cp.async.commit_group;" ::: "memory");
    }

    for (int it = 0; it < niter; ++it) {
        asm volatile("cp.async.wait_group 2;" ::: "memory");
        __syncthreads();
        if (it + 3 < niter) issue_stage((it + 3) & 3, (it + 3) * 32);
        asm volatile("cp.async.commit_group;" ::: "memory");

        const uint32_t sA = sb + (uint32_t)(it & 3) * STG;
        const uint32_t sB = sA + ASTG;
        #pragma unroll
        for (int ks = 0; ks < 2; ++ks) {
            uint32_t af[4][4], bf[8][2];
            #pragma unroll
            for (int mf = 0; mf < 4; ++mf)
                ldmx4(af[mf], sA + (uint32_t)(a_row + mf * 16) * LPB
                              + (uint32_t)(ks * 16 + a_col8) * 2);
            #pragma unroll
            for (int nf2 = 0; nf2 < 4; ++nf2) {
                uint32_t r[4];
                ldmx4(r, sB + (uint32_t)(wn + nf2 * 16 + b_row) * LPB
                         + (uint32_t)(ks * 16 + b_col8) * 2);
                bf[nf2 * 2][0] = r[0]; bf[nf2 * 2][1] = r[1];
                bf[nf2 * 2 + 1][0] = r[2]; bf[nf2 * 2 + 1][1] = r[3];
            }
            #pragma unroll
            for (int mf = 0; mf < 4; ++mf)
                #pragma unroll
                for (int nf = 0; nf < 8; ++nf)
                    mma16816(acc[mf][nf], af[mf], bf[nf]);
        }
    }

    const int erow = lane >> 2, ecol = (lane & 3) * 2;
    if (do_exp) {
        #pragma unroll
        for (int mf = 0; mf < 4; ++mf) {
            float sA = 0.f, sB = 0.f;
            #pragma unroll
            for (int nf = 0; nf < 8; ++nf) {
                const int col = wn + nf * 8 + ecol;
                float e0 = fexp(acc[mf][nf][0]), e1 = fexp(acc[mf][nf][1]);
                float e2 = fexp(acc[mf][nf][2]), e3 = fexp(acc[mf][nf][3]);
                const size_t r0 = (size_t)(m0 + wm + mf * 16 + erow);
                *(float2*)(Cf + r0 * ldc + n0 + col) = make_float2(e0, e1);
                *(float2*)(Cf + (r0 + 8) * ldc + n0 + col) = make_float2(e2, e3);
                sA += e0 + e1;
                sB += e2 + e3;
            }
            sA += __shfl_xor_sync(0xffffffffu, sA, 1);
            sA += __shfl_xor_sync(0xffffffffu, sA, 2);
            sB += __shfl_xor_sync(0xffffffffu, sB, 1);
            sB += __shfl_xor_sync(0xffffffffu, sB, 2);
            if ((lane & 3) == 0) {
                sred[w & 3][wm + mf * 16 + erow] = sA;
                sred[w & 3][wm + mf * 16 + erow + 8] = sB;
            }
        }
        __syncthreads();
        if (tid < 128) {
            float s = sred[0][tid] + sred[1][tid] + sred[2][tid] + sred[3][tid];
            g_psum[(size_t)(m0 + tid) * NTILE + blockIdx.y] = s;
        }
    } else {
        #pragma unroll
        for (int mf = 0; mf < 4; ++mf) {
            #pragma unroll
            for (int nf = 0; nf < 8; ++nf) {
                const int col = wn + nf * 8 + ecol;
                float b0v = bias ? bias[n0 + col] : 0.f;
                float b1v = bias ? bias[n0 + col + 1] : 0.f;
                float v00 = acc[mf][nf][0] + b0v, v01 = acc[mf][nf][1] + b1v;
                float v10 = acc[mf][nf][2] + b0v, v11 = acc[mf][nf][3] + b1v;
                const size_t r0 = (size_t)(m0 + wm + mf * 16 + erow);
                if (Cb) {
                    __nv_bfloat162 p0 = __float22bfloat162_rn(make_float2(v00, v01));
                    __nv_bfloat162 p1 = __float22bfloat162_rn(make_float2(v10, v11));
                    *(uint32_t*)(Cb + r0 * ldc + n0 + col) = *(uint32_t*)&p0;
                    *(uint32_t*)(Cb + (r0 + 8) * ldc + n0 + col) = *(uint32_t*)&p1;
                } else {
                    *(float2*)(Cf + r0 * ldc + n0 + col) = make_float2(v00, v01);
                    *(float2*)(Cf + (r0 + 8) * ldc + n0 + col) = make_float2(v10, v11);
                }
            }
        }
    }
}

// ------------------------- persistent skewed RNN (SMEM-staged) -------------
// lane = (b = lane&7, rr = lane>>3); warp w owns k-slice [w*128, w*128+128).
// Per tick: cooperative h stage -> padded SMEM; conflict-free broadcast LDS.
__global__ __launch_bounds__(256, 1) void rnn_kernel(const float* __restrict__ Wh,
                                                     const float* __restrict__ pre0) {
    extern __shared__ float sm[];
    float* Wsh = sm;                       // [24][1028]
    float* hs0 = sm + 24 * 1028;           // [8][1028]
    float* hs1 = hs0 + 8 * 1028;           // [8][1028]
    float* red = hs1 + 8 * 1028;           // [8 warps][24 rows][8 b]
    const int tid = threadIdx.x;
    const int r0 = blockIdx.x * 8;

    // load 24 weight rows (Wh0 | M10 | Wh1) into padded SMEM
    for (int idx = tid; idx < 24 * 256; idx += 256) {
        int j = idx >> 8, c = (idx & 255) * 4;
        const float* srow;
        if (j < 8)       srow = Wh + (size_t)(r0 + j) * H;
        else if (j < 16) srow = g_M10 + (size_t)(r0 + j - 8) * H;
        else             srow = Wh + (size_t)H * H + (size_t)(r0 + j - 16) * H;
        *(float4*)(Wsh + j * 1028 + c) = __ldg((const float4*)(srow + c));
    }
    // zero this CTA's state slices (both slots, both layers)
    if (tid < 128) {
        int slot = tid >> 6, b = (tid >> 3) & 7, r = tid & 7;
        g_h0buf[slot * (BB * H) + b * H + r0 + r] = 0.f;
        g_h1buf[slot * (BB * H) + b * H + r0 + r] = 0.f;
    }
    grid_barrier();

    const int lane = tid & 31, w = tid >> 5;
    const int b = lane & 7, rr = lane >> 3;
    const float* h0p = hs0 + b * 1028 + w * 128;
    const float* h1p = hs1 + b * 1028 + w * 128;
    const float* w00 = Wsh + (rr * 2) * 1028 + w * 128;
    const float* w01 = Wsh + (rr * 2 + 1) * 1028 + w * 128;
    const float* w10 = Wsh + (8 + rr * 2) * 1028 + w * 128;
    const float* w11 = Wsh + (9 + rr * 2) * 1028 + w * 128;
    const float* w20 = Wsh + (16 + rr * 2) * 1028 + w * 128;
    const float* w21 = Wsh + (17 + rr * 2) * 1028 + w * 128;

    for (int tick = 0; tick <= SS; ++tick) {
        const int rs0 = (tick & 1) ^ 1, rs1 = (tick & 1);
        // stage h0 (hs0[tick-1]) and h1 (hs1[tick-2]) into padded SMEM
        {
            const float* gg0 = g_h0buf + rs0 * (BB * H);
            const float* gg1 = g_h1buf + rs1 * (BB * H);
            for (int c = tid; c < 2048; c += 256) {
                int row = c >> 8, seg = (c & 255) * 4;
                *(float4*)(hs0 + row * 1028 + seg) = ldcg4(gg0 + row * H + seg);
                *(float4*)(hs1 + row * 1028 + seg) = ldcg4(gg1 + row * H + seg);
            }
        }
        __syncthreads();

        ull a00 = 0, a01 = 0, a10 = 0, a11 = 0, a20 = 0, a21 = 0;
        #pragma unroll 8
        for (int i = 0; i < 32; ++i) {
            ulonglong2 h0v = *(const ulonglong2*)(h0p + i * 4);
            ulonglong2 h1v = *(const ulonglong2*)(h1p + i * 4);
            ulonglong2 v00 = *(const ulonglong2*)(w00 + i * 4);
            ulonglong2 v01 = *(const ulonglong2*)(w01 + i * 4);
            ulonglong2 v10 = *(const ulonglong2*)(w10 + i * 4);
            ulonglong2 v11 = *(const ulonglong2*)(w11 + i * 4);
            ulonglong2 v20 = *(const ulonglong2*)(w20 + i * 4);
            ulonglong2 v21 = *(const ulonglong2*)(w21 + i * 4);
            a00 = ffma2(v00.x, h0v.x, a00); a00 = ffma2(v00.y, h0v.y, a00);
            a01 = ffma2(v01.x, h0v.x, a01); a01 = ffma2(v01.y, h0v.y, a01);
            a10 = ffma2(v10.x, h0v.x, a10); a10 = ffma2(v10.y, h0v.y, a10);
            a11 = ffma2(v11.x, h0v.x, a11); a11 = ffma2(v11.y, h0v.y, a11);
            a20 = ffma2(v20.x, h1v.x, a20); a20 = ffma2(v20.y, h1v.y, a20);
            a21 = ffma2(v21.x, h1v.x, a21); a21 = ffma2(v21.y, h1v.y, a21);
        }
        red[w * 192 + (rr * 2) * 8 + b]      = hsum2(a00);
        red[w * 192 + (rr * 2 + 1) * 8 + b]  = hsum2(a01);
        red[w * 192 + (8 + rr * 2) * 8 + b]  = hsum2(a10);
        red[w * 192 + (9 + rr * 2) * 8 + b]  = hsum2(a11);
        red[w * 192 + (16 + rr * 2) * 8 + b] = hsum2(a20);
        red[w * 192 + (17 + rr * 2) * 8 + b] = hsum2(a21);
        __syncthreads();

        if (tid < 64) {
            if (tick < SS) {
                int row = tid >> 3, bb = tid & 7;
                float s = 0.f;
                #pragma unroll
                for (int ww = 0; ww < 8; ++ww) s += red[ww * 192 + row * 8 + bb];
                float v = tanhf(pre0[(size_t)(bb * SS + tick) * H + r0 + row] + s);
                __stcg(&g_h0buf[rs1 * (BB * H) + bb * H + r0 + row], v);
            }
        } else if (tid < 128) {
            if (tick >= 1) {
                int j = tid - 64, row = j >> 3, bb = j & 7;
                float s1 = 0.f, s2 = 0.f;
                #pragma unroll
                for (int ww = 0; ww < 8; ++ww) {
                    s1 += red[ww * 192 + (8 + row) * 8 + bb];
                    s2 += red[ww * 192 + (16 + row) * 8 + bb];
                }
                float v = tanhf(g_c1[r0 + row] + s1 + s2);
                __stcg(&g_h1buf[rs0 * (BB * H) + bb * H + r0 + row], v);
                g_HS1b[(size_t)(bb * SS + tick - 1) * H + r0 + row] = __float2bfloat16(v);
            }
        }
        grid_barrier();
    }
}

// ------------------------- normalize (softmax finish) ----------------------
__global__ __launch_bounds__(256) void normalize_kernel(float* __restrict__ out) {
    __shared__ float sh[256];
    const int row = blockIdx.x, t = threadIdx.x;
    sh[t] = (t < NTILE) ? g_psum[(size_t)row * NTILE + t] : 0.f;
    __syncthreads();
    #pragma unroll
    for (int s = 128; s; s >>= 1) {
        if (t < s) sh[t] += sh[t + s];
        __syncthreads();
    }
    const float inv = 1.0f / sh[0];
    float4* o = (float4*)(out + (size_t)row * VV);
    for (int i = t; i < VV / 4; i += 256) {
        float4 v = o[i];
        v.x *= inv; v.y *= inv; v.z *= inv; v.w *= inv;
        o[i] = v;
    }
}

// ------------------------- launch ------------------------------------------
extern "C" void kernel_launch(void* const* d_in, const int* in_sizes, int n_in,
                              void* d_out, int out_size) {
    const int*   tokens = (const int*)d_in[0];
    const float* E  = (const float*)d_in[1];
    const float* Wi = (const float*)d_in[2];
    const float* bi = (const float*)d_in[3];
    const float* Wh = (const float*)d_in[4];
    const float* bh = (const float*)d_in[5];
    const float* Wo = (const float*)d_in[6];
    const float* bo = (const float*)d_in[7];
    float* out = (float*)d_out;

    cudaFuncSetAttribute(rnn_kernel, cudaFuncAttributeMaxDynamicSharedMemorySize, RNN_SMEM);
    cudaFuncSetAttribute(gemm_bf16_mma, cudaFuncAttributeMaxDynamicSharedMemorySize, GM_SMEM);

    static float *pPre0 = nullptr, *pM10, *pB0;
    static __nv_bfloat16 *pEb, *pXb, *pWib, *pWo0Tb, *pWo1b, *pHS1b, *pYb;
    if (!pPre0) {
        cudaGetSymbolAddress((void**)&pPre0,  g_pre0);
        cudaGetSymbolAddress((void**)&pM10,   g_M10);
        cudaGetSymbolAddress((void**)&pB0,    g_b0);
        cudaGetSymbolAddress((void**)&pEb,    g_Eb);
        cudaGetSymbolAddress((void**)&pXb,    g_Xb);
        cudaGetSymbolAddress((void**)&pWib,   g_Wib);
        cudaGetSymbolAddress((void**)&pWo0Tb, g_Wo0Tb);
        cudaGetSymbolAddress((void**)&pWo1b,  g_Wo1b);
        cudaGetSymbolAddress((void**)&pHS1b,  g_HS1b);
        cudaGetSymbolAddress((void**)&pYb,    g_Yb);
    }

    // 1: all small prep work fused
    fused_prep<<<4736, 256>>>(tokens, E, Wi, bi, bh, Wo, bo);
    // 2: pre0 = X @ Wi0.T + (bi0+bh0)   [fp32]
    gemm_bf16_mma<<<dim3(16, 4), 256, GM_SMEM>>>(pXb, pWib, pB0, pPre0, nullptr, H, H, 0);
    // 3: M10 = Wi1 @ Wo0                [fp32]
    gemm_bf16_mma<<<dim3(8, 4), 256, GM_SMEM>>>(pWib + (size_t)H * H, pWo0Tb, nullptr, pM10, nullptr, H, H, 0);
    // 4: recurrence -> g_HS1b (bf16)    [ncu captures this launch]
    rnn_kernel<<<NB_RNN, 256, RNN_SMEM>>>(Wh, pPre0);
    // 5: E -> bf16
    conv_bf16<<<(VV * H / 8 + 255) / 256, 256>>>(E, pEb, VV * H / 8);
    // 6: Yb = HS1 @ Wo1.T + bo1         [bf16]
    gemm_bf16_mma<<<dim3(16, 4), 256, GM_SMEM>>>(pHS1b, pWo1b, bo + H, nullptr, pYb, H, H, 0);
    // 7: out = exp(Y @ E.T), psum partials
    gemm_bf16_mma<<<dim3(16, NTILE), 256, GM_SMEM>>>(pYb, pEb, nullptr, out, nullptr, H, VV, 1);
    // 8: normalize rows
    normalize_kernel<<<MALL, 256>>>(out);
}

// round 9
// speedup vs baseline: 2.8943x; 1.0114x over previous
#include <cuda_runtime.h>
#include <cuda_bf16.h>
#include <cuda_fp8.h>
#include <cstddef>
#include <cstdint>

typedef unsigned long long ull;

#define H    1024
#define BB   8
#define SS   256
#define VV   32000
#define MALL (BB*SS)          // 2048
#define NB_RNN 128
#define NTILE 125             // logits n-tiles (32000/256)
#define RNN_SMEM ((24*1028 + 16*1028 + 8*192) * 4)   // 170624
#define FP8_SCALE   64.0f
#define FP8_INVSQ   (1.0f / 4096.0f)

// ------------------------- device scratch ----------------------------------
__device__ float g_pre0[MALL * H];
__device__ float g_M10[H * H];
__device__ float g_c1[H];
__device__ float g_b0[H];
__device__ float g_h0buf[2 * BB * H];
__device__ float g_h1buf[2 * BB * H];
__device__ float g_psum[(size_t)MALL * NTILE];
__device__ uint8_t g_E8[(size_t)VV * H];          // 32MB (e4m3, x64)
__device__ uint8_t g_Y8[MALL * H];                // 2MB  (e4m3, x64)
__device__ __nv_bfloat16 g_Xb[MALL * H];
__device__ __nv_bfloat16 g_Wib[2 * H * H];
__device__ __nv_bfloat16 g_Wo0Tb[H * H];
__device__ __nv_bfloat16 g_Wo1b[H * H];
__device__ __nv_bfloat16 g_HS1b[MALL * H];
__device__ volatile unsigned g_bar_gen;
__device__ unsigned g_bar_cnt;

// ------------------------- helpers -----------------------------------------
__device__ __forceinline__ ull ffma2(ull a, ull b, ull c) {
    ull d;
    asm("fma.rn.f32x2 %0, %1, %2, %3;" : "=l"(d) : "l"(a), "l"(b), "l"(c));
    return d;
}
__device__ __forceinline__ float2 unpack2(ull v) {
    float x, y;
    asm("mov.b64 {%0, %1}, %2;" : "=f"(x), "=f"(y) : "l"(v));
    return make_float2(x, y);
}
__device__ __forceinline__ float hsum2(ull a) {
    float2 p = unpack2(a);
    return p.x + p.y;
}
__device__ __forceinline__ float4 ldcg4(const float* p) {
    float4 v;
    asm volatile("ld.global.cg.v4.f32 {%0,%1,%2,%3}, [%4];"
                 : "=f"(v.x), "=f"(v.y), "=f"(v.z), "=f"(v.w) : "l"(p));
    return v;
}
__device__ __forceinline__ uint32_t smem_u32(const void* p) {
    uint32_t a;
    asm("{ .reg .u64 t; cvta.to.shared.u64 t, %1; cvt.u32.u64 %0, t; }"
        : "=r"(a) : "l"(p));
    return a;
}
__device__ __forceinline__ void cpasync16(uint32_t dst, const void* src) {
    asm volatile("cp.async.cg.shared.global [%0], [%1], 16;"
                 :: "r"(dst), "l"(src));
}
__device__ __forceinline__ void ldmx4(uint32_t* r, uint32_t addr) {
    asm volatile("ldmatrix.sync.aligned.m8n8.x4.shared.b16 {%0,%1,%2,%3}, [%4];"
                 : "=r"(r[0]), "=r"(r[1]), "=r"(r[2]), "=r"(r[3]) : "r"(addr));
}
__device__ __forceinline__ void mma16816(float* d, const uint32_t* a, const uint32_t* b) {
    asm volatile(
        "mma.sync.aligned.m16n8k16.row.col.f32.bf16.bf16.f32 "
        "{%0,%1,%2,%3}, {%4,%5,%6,%7}, {%8,%9}, {%0,%1,%2,%3};"
        : "+f"(d[0]), "+f"(d[1]), "+f"(d[2]), "+f"(d[3])
        : "r"(a[0]), "r"(a[1]), "r"(a[2]), "r"(a[3]), "r"(b[0]), "r"(b[1]));
}
__device__ __forceinline__ void mma16832f8(float* d, const uint32_t* a, const uint32_t* b) {
    asm volatile(
        "mma.sync.aligned.m16n8k32.row.col.f32.e4m3.e4m3.f32 "
        "{%0,%1,%2,%3}, {%4,%5,%6,%7}, {%8,%9}, {%0,%1,%2,%3};"
        : "+f"(d[0]), "+f"(d[1]), "+f"(d[2]), "+f"(d[3])
        : "r"(a[0]), "r"(a[1]), "r"(a[2]), "r"(a[3]), "r"(b[0]), "r"(b[1]));
}
// fast exp on fma/alu pipes (|x| < ~80; rel err ~4e-5)
__device__ __forceinline__ float fexp(float x) {
    float km = fmaf(x, 1.4426950408889634f, 12582912.0f);
    int   ik = __float_as_int(km) - 0x4B400000;
    float kf = km - 12582912.0f;
    float f  = fmaf(kf, -0.6931471805599453f, x);
    float p  = fmaf(f, 0.041666668f, 0.16666667f);
    p = fmaf(p, f, 0.5f);
    p = fmaf(p, f, 1.0f);
    p = fmaf(p, f, 1.0f);
    return __int_as_float(__float_as_int(p) + (ik << 23));
}
__device__ __forceinline__ uint16_t to_fp8x2(float lo, float hi) {
    return (uint16_t)__nv_cvt_float2_to_fp8x2(make_float2(lo, hi),
                                              __NV_SATFINITE, __NV_E4M3);
}

// ------------------------- grid barrier ------------------------------------
__device__ __forceinline__ void grid_barrier() {
    __threadfence();
    __syncthreads();
    if (threadIdx.x == 0) {
        unsigned my = g_bar_gen;
        unsigned t = atomicAdd(&g_bar_cnt, 1u);
        if (t == NB_RNN - 1u) {
            g_bar_cnt = 0u;
            __threadfence();
            g_bar_gen = my + 1u;
        } else {
            while (g_bar_gen == my) { }
        }
        __threadfence();
    }
    __syncthreads();
}

// ------------------------- fused prep (launch #1) --------------------------
__global__ __launch_bounds__(256) void fused_prep(
    const int* __restrict__ tokens, const float* __restrict__ E,
    const float* __restrict__ Wi, const float* __restrict__ bi,
    const float* __restrict__ bh, const float* __restrict__ Wo,
    const float* __restrict__ bo)
{
    __shared__ float tbuf[32][33];
    const int bx = blockIdx.x, t = threadIdx.x;
    if (bx < 2048) {                       // gather -> g_Xb (bf16)
        int b = bx >> 8, tt = bx & 255;
        int tok = tokens[b * SS + tt];
        float4 v = __ldg((const float4*)(E + (size_t)tok * H) + t);
        __nv_bfloat162 lo = __float22bfloat162_rn(make_float2(v.x, v.y));
        __nv_bfloat162 hi = __float22bfloat162_rn(make_float2(v.z, v.w));
        uint2 u;
        u.x = *(uint32_t*)&lo; u.y = *(uint32_t*)&hi;
        ((uint2*)(g_Xb + (size_t)bx * H))[t] = u;
    } else if (bx < 3072) {                // Wo0 transpose -> g_Wo0Tb
        int id = bx - 2048;
        int bxt = (id & 31) * 32, byt = (id >> 5) * 32;
        int tx = t & 31, ty = t >> 5;
        for (int j = ty; j < 32; j += 8)
            tbuf[j][tx] = Wo[(size_t)(byt + j) * H + bxt + tx];
        __syncthreads();
        for (int j = ty; j < 32; j += 8)
            g_Wo0Tb[(size_t)(bxt + j) * H + byt + tx] = __float2bfloat16(tbuf[tx][j]);
    } else if (bx < 3200) {                // bias prep -> g_c1, g_b0
        int w = t >> 5, lane = t & 31;
        int r = (bx - 3072) * 8 + w;
        const float* Wi1r = Wi + (size_t)H * H + (size_t)r * H;
        float s = 0.f;
        for (int k = lane; k < H; k += 32) s += Wi1r[k] * bo[k];
        #pragma unroll
        for (int off = 16; off; off >>= 1) s += __shfl_xor_sync(0xffffffffu, s, off);
        if (lane == 0) {
            g_c1[r] = s + bi[H + r] + bh[H + r];
            g_b0[r] = bi[r] + bh[r];
        }
    } else if (bx < 4224) {                // conv Wi -> g_Wib
        int i = (bx - 3200) * 256 + t;
        const float4* p = (const float4*)Wi + (size_t)i * 2;
        float4 a = __ldg(p), b = __ldg(p + 1);
        __nv_bfloat162 r0 = __float22bfloat162_rn(make_float2(a.x, a.y));
        __nv_bfloat162 r1 = __float22bfloat162_rn(make_float2(a.z, a.w));
        __nv_bfloat162 r2 = __float22bfloat162_rn(make_float2(b.x, b.y));
        __nv_bfloat162 r3 = __float22bfloat162_rn(make_float2(b.z, b.w));
        uint4 u;
        u.x = *(uint32_t*)&r0; u.y = *(uint32_t*)&r1;
        u.z = *(uint32_t*)&r2; u.w = *(uint32_t*)&r3;
        ((uint4*)g_Wib)[i] = u;
    } else {                               // conv Wo1 -> g_Wo1b
        int i = (bx - 4224) * 256 + t;
        const float4* p = (const float4*)(Wo + (size_t)H * H) + (size_t)i * 2;
        float4 a = __ldg(p), b = __ldg(p + 1);
        __nv_bfloat162 r0 = __float22bfloat162_rn(make_float2(a.x, a.y));
        __nv_bfloat162 r1 = __float22bfloat162_rn(make_float2(a.z, a.w));
        __nv_bfloat162 r2 = __float22bfloat162_rn(make_float2(b.x, b.y));
        __nv_bfloat162 r3 = __float22bfloat162_rn(make_float2(b.z, b.w));
        uint4 u;
        u.x = *(uint32_t*)&r0; u.y = *(uint32_t*)&r1;
        u.z = *(uint32_t*)&r2; u.w = *(uint32_t*)&r3;
        ((uint4*)g_Wo1b)[i] = u;
    }
}

// ------------------------- E -> fp8 (x64) ----------------------------------
__global__ __launch_bounds__(256) void conv_fp8(const float* __restrict__ in,
                                                uint8_t* __restrict__ out, int n8) {
    int i = blockIdx.x * 256 + threadIdx.x;
    if (i >= n8) return;
    const float4* p = (const float4*)in + (size_t)i * 2;
    float4 a = __ldg(p), b = __ldg(p + 1);
    uint16_t q0 = to_fp8x2(a.x * FP8_SCALE, a.y * FP8_SCALE);
    uint16_t q1 = to_fp8x2(a.z * FP8_SCALE, a.w * FP8_SCALE);
    uint16_t q2 = to_fp8x2(b.x * FP8_SCALE, b.y * FP8_SCALE);
    uint16_t q3 = to_fp8x2(b.z * FP8_SCALE, b.w * FP8_SCALE);
    uint2 u;
    u.x = (uint32_t)q0 | ((uint32_t)q1 << 16);
    u.y = (uint32_t)q2 | ((uint32_t)q3 << 16);
    ((uint2*)out)[i] = u;
}

// ------------------------- bf16 mma.sync NT GEMM, 128x256 tile, 4 stages ---
// C = bias + A@B^T.  Out: Cf fp32, or Cb bf16, or C8 fp8 (x64 scale).
#define LPB     80
#define ASTG    (128 * LPB)
#define BSTG    (256 * LPB)
#define STG     (ASTG + BSTG)
#define GM_SMEM (4 * STG)                 // 122880
__global__ __launch_bounds__(256, 1) void gemm_bf16_mma(
    const __nv_bfloat16* __restrict__ A,
    const __nv_bfloat16* __restrict__ B,
    const float* __restrict__ bias,
    float* __restrict__ Cf,
    __nv_bfloat16* __restrict__ Cb,
    uint8_t* __restrict__ C8,
    int K, int ldc)
{
    extern __shared__ __align__(16) char smem[];
    const uint32_t sb = smem_u32(smem);
    const int tid = threadIdx.x;
    const int m0 = blockIdx.x * 128, n0 = blockIdx.y * 256;
    const int niter = K >> 5;

    float acc[4][8][4];
    #pragma unroll
    for (int i = 0; i < 4; i++)
        #pragma unroll
        for (int j = 0; j < 8; j++)
            #pragma unroll
            for (int q = 0; q < 4; q++) acc[i][j][q] = 0.f;

    const int w = tid >> 5, lane = tid & 31;
    const int wm = (w >> 2) * 64, wn = (w & 3) * 64;
    const int a_row = wm + ((lane >> 3) & 1) * 8 + (lane & 7);
    const int a_col8 = ((lane >> 4) & 1) * 8;
    const int b_row = ((lane >> 4) & 1) * 8 + (lane & 7);
    const int b_col8 = ((lane >> 3) & 1) * 8;

    auto issue_stage = [&](int s, int ko) {
        const uint32_t sA = sb + (uint32_t)s * STG;
        const uint32_t sB = sA + ASTG;
        #pragma unroll
        for (int j = 0; j < 2; ++j) {
            int c = tid + 256 * j;
            int row = c >> 2, col = (c & 3) * 8;
            cpasync16(sA + (uint32_t)row * LPB + (uint32_t)(c & 3) * 16,
                      A + (size_t)(m0 + row) * K + ko + col);
        }
        #pragma unroll
        for (int j = 0; j < 4; ++j) {
            int c = tid + 256 * j;
            int row = c >> 2, col = (c & 3) * 8;
            cpasync16(sB + (uint32_t)row * LPB + (uint32_t)(c & 3) * 16,
                      B + (size_t)(n0 + row) * K + ko + col);
        }
    };

    #pragma unroll
    for (int s = 0; s < 3; ++s) {
        issue_stage(s, s * 32);
        asm volatile("cp.async.commit_group;" ::: "memory");
    }

    for (int it = 0; it < niter; ++it) {
        asm volatile("cp.async.wait_group 2;" ::: "memory");
        __syncthreads();
        if (it + 3 < niter) issue_stage((it + 3) & 3, (it + 3) * 32);
        asm volatile("cp.async.commit_group;" ::: "memory");

        const uint32_t sA = sb + (uint32_t)(it & 3) * STG;
        const uint32_t sB = sA + ASTG;
        #pragma unroll
        for (int ks = 0; ks < 2; ++ks) {
            uint32_t af[4][4], bf[8][2];
            #pragma unroll
            for (int mf = 0; mf < 4; ++mf)
                ldmx4(af[mf], sA + (uint32_t)(a_row + mf * 16) * LPB
                              + (uint32_t)(ks * 16 + a_col8) * 2);
            #pragma unroll
            for (int nf2 = 0; nf2 < 4; ++nf2) {
                uint32_t r[4];
                ldmx4(r, sB + (uint32_t)(wn + nf2 * 16 + b_row) * LPB
                         + (uint32_t)(ks * 16 + b_col8) * 2);
                bf[nf2 * 2][0] = r[0]; bf[nf2 * 2][1] = r[1];
                bf[nf2 * 2 + 1][0] = r[2]; bf[nf2 * 2 + 1][1] = r[3];
            }
            #pragma unroll
            for (int mf = 0; mf < 4; ++mf)
                #pragma unroll
                for (int nf = 0; nf < 8; ++nf)
                    mma16816(acc[mf][nf], af[mf], bf[nf]);
        }
    }

    const int erow = lane >> 2, ecol = (lane & 3) * 2;
    #pragma unroll
    for (int mf = 0; mf < 4; ++mf) {
        #pragma unroll
        for (int nf = 0; nf < 8; ++nf) {
            const int col = wn + nf * 8 + ecol;
            float b0v = bias ? bias[n0 + col] : 0.f;
            float b1v = bias ? bias[n0 + col + 1] : 0.f;
            float v00 = acc[mf][nf][0] + b0v, v01 = acc[mf][nf][1] + b1v;
            float v10 = acc[mf][nf][2] + b0v, v11 = acc[mf][nf][3] + b1v;
            const size_t r0 = (size_t)(m0 + wm + mf * 16 + erow);
            if (C8) {
                *(uint16_t*)(C8 + r0 * ldc + n0 + col) =
                    to_fp8x2(v00 * FP8_SCALE, v01 * FP8_SCALE);
                *(uint16_t*)(C8 + (r0 + 8) * ldc + n0 + col) =
                    to_fp8x2(v10 * FP8_SCALE, v11 * FP8_SCALE);
            } else if (Cb) {
                __nv_bfloat162 p0 = __float22bfloat162_rn(make_float2(v00, v01));
                __nv_bfloat162 p1 = __float22bfloat162_rn(make_float2(v10, v11));
                *(uint32_t*)(Cb + r0 * ldc + n0 + col) = *(uint32_t*)&p0;
                *(uint32_t*)(Cb + (r0 + 8) * ldc + n0 + col) = *(uint32_t*)&p1;
            } else {
                *(float2*)(Cf + r0 * ldc + n0 + col) = make_float2(v00, v01);
                *(float2*)(Cf + (r0 + 8) * ldc + n0 + col) = make_float2(v10, v11);
            }
        }
    }
}

// ------------------------- fp8 logits GEMM + exp epilogue ------------------
// out = exp((Y8 @ E8^T)/4096); per-(row, n-CTA) partial sums -> g_psum.
// Identical structure; k-iter covers 64 fp8 (2 x k32 mma). LPB = 64B + 16 pad.
__global__ __launch_bounds__(256, 1) void gemm_fp8_logits(
    const uint8_t* __restrict__ A,
    const uint8_t* __restrict__ B,
    float* __restrict__ out)
{
    extern __shared__ __align__(16) char smem[];
    __shared__ float sred[4][128];
    const uint32_t sb = smem_u32(smem);
    const int tid = threadIdx.x;
    const int m0 = blockIdx.x * 128, n0 = blockIdx.y * 256;
    const int niter = H >> 6;     // 16

    float acc[4][8][4];
    #pragma unroll
    for (int i = 0; i < 4; i++)
        #pragma unroll
        for (int j = 0; j < 8; j++)
            #pragma unroll
            for (int q = 0; q < 4; q++) acc[i][j][q] = 0.f;

    const int w = tid >> 5, lane = tid & 31;
    const int wm = (w >> 2) * 64, wn = (w & 3) * 64;
    const int a_row = wm + ((lane >> 3) & 1) * 8 + (lane & 7);
    const int a_col8 = ((lane >> 4) & 1) * 8;      // b16-pair units
    const int b_row = ((lane >> 4) & 1) * 8 + (lane & 7);
    const int b_col8 = ((lane >> 3) & 1) * 8;

    auto issue_stage = [&](int s, int ko) {        // ko in fp8 elems (bytes)
        const uint32_t sA = sb + (uint32_t)s * STG;
        const uint32_t sB = sA + ASTG;
        #pragma unroll
        for (int j = 0; j < 2; ++j) {
            int c = tid + 256 * j;
            int row = c >> 2, col = (c & 3) * 16;
            cpasync16(sA + (uint32_t)row * LPB + (uint32_t)(c & 3) * 16,
                      A + (size_t)(m0 + row) * H + ko + col);
        }
        #pragma unroll
        for (int j = 0; j < 4; ++j) {
            int c = tid + 256 * j;
            int row = c >> 2, col = (c & 3) * 16;
            cpasync16(sB + (uint32_t)row * LPB + (uint32_t)(c & 3) * 16,
                      B + (size_t)(n0 + row) * H + ko + col);
        }
    };

    #pragma unroll
    for (int s = 0; s < 3; ++s) {
        issue_stage(s, s * 64);
        asm volatile("cp.async.commit_group;" ::: "memory");
    }

    for (int it = 0; it < niter; ++it) {
        asm volatile("cp.async.wait_group 2;" ::: "memory");
        __syncthreads();
        if (it + 3 < niter) issue_stage((it + 3) & 3, (it + 3) * 64);
        asm volatile("cp.async.commit_group;" ::: "memory");

        const uint32_t sA = sb + (uint32_t)(it & 3) * STG;
        const uint32_t sB = sA + ASTG;
        #pragma unroll
        for (int ks = 0; ks < 2; ++ks) {           // each ks: 32 fp8 of k
            uint32_t af[4][4], bf[8][2];
            #pragma unroll
            for (int mf = 0; mf < 4; ++mf)
                ldmx4(af[mf], sA + (uint32_t)(a_row + mf * 16) * LPB
                              + (uint32_t)(ks * 16 + a_col8) * 2);
            #pragma unroll
            for (int nf2 = 0; nf2 < 4; ++nf2) {
                uint32_t r[4];
                ldmx4(r, sB + (uint32_t)(wn + nf2 * 16 + b_row) * LPB
                         + (uint32_t)(ks * 16 + b_col8) * 2);
                bf[nf2 * 2][0] = r[0]; bf[nf2 * 2][1] = r[1];
                bf[nf2 * 2 + 1][0] = r[2]; bf[nf2 * 2 + 1][1] = r[3];
            }
            #pragma unroll
            for (int mf = 0; mf < 4; ++mf)
                #pragma unroll
                for (int nf = 0; nf < 8; ++nf)
                    mma16832f8(acc[mf][nf], af[mf], bf[nf]);
        }
    }

    const int erow = lane >> 2, ecol = (lane & 3) * 2;
    #pragma unroll
    for (int mf = 0; mf < 4; ++mf) {
        float sA = 0.f, sB = 0.f;
        #pragma unroll
        for (int nf = 0; nf < 8; ++nf) {
            const int col = wn + nf * 8 + ecol;
            float e0 = fexp(acc[mf][nf][0] * FP8_INVSQ);
            float e1 = fexp(acc[mf][nf][1] * FP8_INVSQ);
            float e2 = fexp(acc[mf][nf][2] * FP8_INVSQ);
            float e3 = fexp(acc[mf][nf][3] * FP8_INVSQ);
            const size_t r0 = (size_t)(m0 + wm + mf * 16 + erow);
            *(float2*)(out + r0 * VV + n0 + col) = make_float2(e0, e1);
            *(float2*)(out + (r0 + 8) * VV + n0 + col) = make_float2(e2, e3);
            sA += e0 + e1;
            sB += e2 + e3;
        }
        sA += __shfl_xor_sync(0xffffffffu, sA, 1);
        sA += __shfl_xor_sync(0xffffffffu, sA, 2);
        sB += __shfl_xor_sync(0xffffffffu, sB, 1);
        sB += __shfl_xor_sync(0xffffffffu, sB, 2);
        if ((lane & 3) == 0) {
            sred[w & 3][wm + mf * 16 + erow] = sA;
            sred[w & 3][wm + mf * 16 + erow + 8] = sB;
        }
    }
    __syncthreads();
    if (tid < 128) {
        float s = sred[0][tid] + sred[1][tid] + sred[2][tid] + sred[3][tid];
        g_psum[(size_t)(m0 + tid) * NTILE + blockIdx.y] = s;
    }
}

// ------------------------- persistent skewed RNN (SMEM-staged) -------------
__global__ __launch_bounds__(256, 1) void rnn_kernel(const float* __restrict__ Wh,
                                                     const float* __restrict__ pre0) {
    extern __shared__ float sm[];
    float* Wsh = sm;                       // [24][1028]
    float* hs0 = sm + 24 * 1028;           // [8][1028]
    float* hs1 = hs0 + 8 * 1028;           // [8][1028]
    float* red = hs1 + 8 * 1028;           // [8 warps][24 rows][8 b]
    const int tid = threadIdx.x;
    const int r0 = blockIdx.x * 8;

    for (int idx = tid; idx < 24 * 256; idx += 256) {
        int j = idx >> 8, c = (idx & 255) * 4;
        const float* srow;
        if (j < 8)       srow = Wh + (size_t)(r0 + j) * H;
        else if (j < 16) srow = g_M10 + (size_t)(r0 + j - 8) * H;
        else             srow = Wh + (size_t)H * H + (size_t)(r0 + j - 16) * H;
        *(float4*)(Wsh + j * 1028 + c) = __ldg((const float4*)(srow + c));
    }
    if (tid < 128) {
        int slot = tid >> 6, b = (tid >> 3) & 7, r = tid & 7;
        g_h0buf[slot * (BB * H) + b * H + r0 + r] = 0.f;
        g_h1buf[slot * (BB * H) + b * H + r0 + r] = 0.f;
    }
    grid_barrier();

    const int lane = tid & 31, w = tid >> 5;
    const int b = lane & 7, rr = lane >> 3;
    const float* h0p = hs0 + b * 1028 + w * 128;
    const float* h1p = hs1 + b * 1028 + w * 128;
    const float* w00 = Wsh + (rr * 2) * 1028 + w * 128;
    const float* w01 = Wsh + (rr * 2 + 1) * 1028 + w * 128;
    const float* w10 = Wsh + (8 + rr * 2) * 1028 + w * 128;
    const float* w11 = Wsh + (9 + rr * 2) * 1028 + w * 128;
    const float* w20 = Wsh + (16 + rr * 2) * 1028 + w * 128;
    const float* w21 = Wsh + (17 + rr * 2) * 1028 + w * 128;

    for (int tick = 0; tick <= SS; ++tick) {
        const int rs0 = (tick & 1) ^ 1, rs1 = (tick & 1);
        {
            const float* gg0 = g_h0buf + rs0 * (BB * H);
            const float* gg1 = g_h1buf + rs1 * (BB * H);
            for (int c = tid; c < 2048; c += 256) {
                int row = c >> 8, seg = (c & 255) * 4;
                *(float4*)(hs0 + row * 1028 + seg) = ldcg4(gg0 + row * H + seg);
                *(float4*)(hs1 + row * 1028 + seg) = ldcg4(gg1 + row * H + seg);
            }
        }
        __syncthreads();

        ull a00 = 0, a01 = 0, a10 = 0, a11 = 0, a20 = 0, a21 = 0;
        #pragma unroll 8
        for (int i = 0; i < 32; ++i) {
            ulonglong2 h0v = *(const ulonglong2*)(h0p + i * 4);
            ulonglong2 h1v = *(const ulonglong2*)(h1p + i * 4);
            ulonglong2 v00 = *(const ulonglong2*)(w00 + i * 4);
            ulonglong2 v01 = *(const ulonglong2*)(w01 + i * 4);
            ulonglong2 v10 = *(const ulonglong2*)(w10 + i * 4);
            ulonglong2 v11 = *(const ulonglong2*)(w11 + i * 4);
            ulonglong2 v20 = *(const ulonglong2*)(w20 + i * 4);
            ulonglong2 v21 = *(const ulonglong2*)(w21 + i * 4);
            a00 = ffma2(v00.x, h0v.x, a00); a00 = ffma2(v00.y, h0v.y, a00);
            a01 = ffma2(v01.x, h0v.x, a01); a01 = ffma2(v01.y, h0v.y, a01);
            a10 = ffma2(v10.x, h0v.x, a10); a10 = ffma2(v10.y, h0v.y, a10);
            a11 = ffma2(v11.x, h0v.x, a11); a11 = ffma2(v11.y, h0v.y, a11);
            a20 = ffma2(v20.x, h1v.x, a20); a20 = ffma2(v20.y, h1v.y, a20);
            a21 = ffma2(v21.x, h1v.x, a21); a21 = ffma2(v21.y, h1v.y, a21);
        }
        red[w * 192 + (rr * 2) * 8 + b]      = hsum2(a00);
        red[w * 192 + (rr * 2 + 1) * 8 + b]  = hsum2(a01);
        red[w * 192 + (8 + rr * 2) * 8 + b]  = hsum2(a10);
        red[w * 192 + (9 + rr * 2) * 8 + b]  = hsum2(a11);
        red[w * 192 + (16 + rr * 2) * 8 + b] = hsum2(a20);
        red[w * 192 + (17 + rr * 2) * 8 + b] = hsum2(a21);
        __syncthreads();

        if (tid < 64) {
            if (tick < SS) {
                int row = tid >> 3, bb = tid & 7;
                float s = 0.f;
                #pragma unroll
                for (int ww = 0; ww < 8; ++ww) s += red[ww * 192 + row * 8 + bb];
                float v = tanhf(pre0[(size_t)(bb * SS + tick) * H + r0 + row] + s);
                __stcg(&g_h0buf[rs1 * (BB * H) + bb * H + r0 + row], v);
            }
        } else if (tid < 128) {
            if (tick >= 1) {
                int j = tid - 64, row = j >> 3, bb = j & 7;
                float s1 = 0.f, s2 = 0.f;
                #pragma unroll
                for (int ww = 0; ww < 8; ++ww) {
                    s1 += red[ww * 192 + (8 + row) * 8 + bb];
                    s2 += red[ww * 192 + (16 + row) * 8 + bb];
                }
                float v = tanhf(g_c1[r0 + row] + s1 + s2);
                __stcg(&g_h1buf[rs0 * (BB * H) + bb * H + r0 + row], v);
                g_HS1b[(size_t)(bb * SS + tick - 1) * H + r0 + row] = __float2bfloat16(v);
            }
        }
        grid_barrier();
    }
}

// ------------------------- normalize (softmax finish) ----------------------
__global__ __launch_bounds__(256) void normalize_kernel(float* __restrict__ out) {
    __shared__ float sh[256];
    const int row = blockIdx.x, t = threadIdx.x;
    sh[t] = (t < NTILE) ? g_psum[(size_t)row * NTILE + t] : 0.f;
    __syncthreads();
    #pragma unroll
    for (int s = 128; s; s >>= 1) {
        if (t < s) sh[t] += sh[t + s];
        __syncthreads();
    }
    const float inv = 1.0f / sh[0];
    float4* o = (float4*)(out + (size_t)row * VV);
    for (int i = t; i < VV / 4; i += 256) {
        float4 v = o[i];
        v.x *= inv; v.y *= inv; v.z *= inv; v.w *= inv;
        o[i] = v;
    }
}

// ------------------------- launch ------------------------------------------
extern "C" void kernel_launch(void* const* d_in, const int* in_sizes, int n_in,
                              void* d_out, int out_size) {
    const int*   tokens = (const int*)d_in[0];
    const float* E  = (const float*)d_in[1];
    const float* Wi = (const float*)d_in[2];
    const float* bi = (const float*)d_in[3];
    const float* Wh = (const float*)d_in[4];
    const float* bh = (const float*)d_in[5];
    const float* Wo = (const float*)d_in[6];
    const float* bo = (const float*)d_in[7];
    float* out = (float*)d_out;

    cudaFuncSetAttribute(rnn_kernel, cudaFuncAttributeMaxDynamicSharedMemorySize, RNN_SMEM);
    cudaFuncSetAttribute(gemm_bf16_mma, cudaFuncAttributeMaxDynamicSharedMemorySize, GM_SMEM);
    cudaFuncSetAttribute(gemm_fp8_logits, cudaFuncAttributeMaxDynamicSharedMemorySize, GM_SMEM);

    static float *pPre0 = nullptr, *pM10, *pB0;
    static uint8_t *pE8, *pY8;
    static __nv_bfloat16 *pXb, *pWib, *pWo0Tb, *pWo1b, *pHS1b;
    if (!pPre0) {
        cudaGetSymbolAddress((void**)&pPre0,  g_pre0);
        cudaGetSymbolAddress((void**)&pM10,   g_M10);
        cudaGetSymbolAddress((void**)&pB0,    g_b0);
        cudaGetSymbolAddress((void**)&pE8,    g_E8);
        cudaGetSymbolAddress((void**)&pY8,    g_Y8);
        cudaGetSymbolAddress((void**)&pXb,    g_Xb);
        cudaGetSymbolAddress((void**)&pWib,   g_Wib);
        cudaGetSymbolAddress((void**)&pWo0Tb, g_Wo0Tb);
        cudaGetSymbolAddress((void**)&pWo1b,  g_Wo1b);
        cudaGetSymbolAddress((void**)&pHS1b,  g_HS1b);
    }

    // 1: all small prep work fused
    fused_prep<<<4736, 256>>>(tokens, E, Wi, bi, bh, Wo, bo);
    // 2: pre0 = X @ Wi0.T + (bi0+bh0)   [fp32]
    gemm_bf16_mma<<<dim3(16, 4), 256, GM_SMEM>>>(pXb, pWib, pB0, pPre0, nullptr, nullptr, H, H);
    // 3: M10 = Wi1 @ Wo0                [fp32]
    gemm_bf16_mma<<<dim3(8, 4), 256, GM_SMEM>>>(pWib + (size_t)H * H, pWo0Tb, nullptr, pM10, nullptr, nullptr, H, H);
    // 4: recurrence -> g_HS1b (bf16)
    rnn_kernel<<<NB_RNN, 256, RNN_SMEM>>>(Wh, pPre0);
    // 5: E -> fp8 (x64)
    conv_fp8<<<(VV * H / 8 + 255) / 256, 256>>>(E, pE8, VV * H / 8);
    // 6: Y8 = fp8(x64)(HS1 @ Wo1.T + bo1)
    gemm_bf16_mma<<<dim3(16, 4), 256, GM_SMEM>>>(pHS1b, pWo1b, bo + H, nullptr, nullptr, pY8, H, H);
    // 7: out = exp((Y8 @ E8^T)/4096), psum partials
    gemm_fp8_logits<<<dim3(16, NTILE), 256, GM_SMEM>>>(pY8, pE8, out);
    // 8: normalize rows
    normalize_kernel<<<MALL, 256>>>(out);
}

// round 10
// speedup vs baseline: 2.9461x; 1.0179x over previous
#include <cuda_runtime.h>
#include <cuda_bf16.h>
#include <cuda_fp8.h>
#include <cstddef>
#include <cstdint>

typedef unsigned long long ull;

#define H    1024
#define BB   8
#define SS   256
#define VV   32000
#define MALL (BB*SS)          // 2048
#define NB_RNN 128
#define NTILE 125             // logits n-tiles (32000/256)
#define RNN_SMEM ((24*1028 + 16*1028 + 8*192) * 4)   // 170624
#define FP8_SCALE   64.0f
#define FP8_INVSQ   (1.0f / 4096.0f)

// ------------------------- device scratch ----------------------------------
__device__ float g_pre0[MALL * H];
__device__ float g_M10[H * H];
__device__ float g_c1[H];
__device__ float g_b0[H];
__device__ float g_h0buf[2 * BB * H];
__device__ float g_h1buf[2 * BB * H];
__device__ float g_psum[(size_t)MALL * NTILE];
__device__ uint8_t g_E8[(size_t)VV * H];          // 32MB (e4m3, x64)
__device__ uint8_t g_Y8[MALL * H];                // 2MB  (e4m3, x64)
__device__ __nv_bfloat16 g_Xb[MALL * H];
__device__ __nv_bfloat16 g_Wib[2 * H * H];
__device__ __nv_bfloat16 g_Wo0Tb[H * H];
__device__ __nv_bfloat16 g_Wo1b[H * H];
__device__ __nv_bfloat16 g_HS1b[MALL * H];
__device__ volatile unsigned g_bar_gen;
__device__ unsigned g_bar_cnt;

// ------------------------- helpers -----------------------------------------
__device__ __forceinline__ ull ffma2(ull a, ull b, ull c) {
    ull d;
    asm("fma.rn.f32x2 %0, %1, %2, %3;" : "=l"(d) : "l"(a), "l"(b), "l"(c));
    return d;
}
__device__ __forceinline__ float2 unpack2(ull v) {
    float x, y;
    asm("mov.b64 {%0, %1}, %2;" : "=f"(x), "=f"(y) : "l"(v));
    return make_float2(x, y);
}
__device__ __forceinline__ float hsum2(ull a) {
    float2 p = unpack2(a);
    return p.x + p.y;
}
__device__ __forceinline__ float4 ldcg4(const float* p) {
    float4 v;
    asm volatile("ld.global.cg.v4.f32 {%0,%1,%2,%3}, [%4];"
                 : "=f"(v.x), "=f"(v.y), "=f"(v.z), "=f"(v.w) : "l"(p));
    return v;
}
__device__ __forceinline__ uint32_t smem_u32(const void* p) {
    uint32_t a;
    asm("{ .reg .u64 t; cvta.to.shared.u64 t, %1; cvt.u32.u64 %0, t; }"
        : "=r"(a) : "l"(p));
    return a;
}
__device__ __forceinline__ void cpasync16(uint32_t dst, const void* src) {
    asm volatile("cp.async.cg.shared.global [%0], [%1], 16;"
                 :: "r"(dst), "l"(src));
}
__device__ __forceinline__ void ldmx4(uint32_t* r, uint32_t addr) {
    asm volatile("ldmatrix.sync.aligned.m8n8.x4.shared.b16 {%0,%1,%2,%3}, [%4];"
                 : "=r"(r[0]), "=r"(r[1]), "=r"(r[2]), "=r"(r[3]) : "r"(addr));
}
__device__ __forceinline__ void mma16816(float* d, const uint32_t* a, const uint32_t* b) {
    asm volatile(
        "mma.sync.aligned.m16n8k16.row.col.f32.bf16.bf16.f32 "
        "{%0,%1,%2,%3}, {%4,%5,%6,%7}, {%8,%9}, {%0,%1,%2,%3};"
        : "+f"(d[0]), "+f"(d[1]), "+f"(d[2]), "+f"(d[3])
        : "r"(a[0]), "r"(a[1]), "r"(a[2]), "r"(a[3]), "r"(b[0]), "r"(b[1]));
}
__device__ __forceinline__ void mma16832f8(float* d, const uint32_t* a, const uint32_t* b) {
    asm volatile(
        "mma.sync.aligned.m16n8k32.row.col.f32.e4m3.e4m3.f32 "
        "{%0,%1,%2,%3}, {%4,%5,%6,%7}, {%8,%9}, {%0,%1,%2,%3};"
        : "+f"(d[0]), "+f"(d[1]), "+f"(d[2]), "+f"(d[3])
        : "r"(a[0]), "r"(a[1]), "r"(a[2]), "r"(a[3]), "r"(b[0]), "r"(b[1]));
}
// fast exp on fma/alu pipes (|x| < ~80; rel err ~4e-5)
__device__ __forceinline__ float fexp(float x) {
    float km = fmaf(x, 1.4426950408889634f, 12582912.0f);
    int   ik = __float_as_int(km) - 0x4B400000;
    float kf = km - 12582912.0f;
    float f  = fmaf(kf, -0.6931471805599453f, x);
    float p  = fmaf(f, 0.041666668f, 0.16666667f);
    p = fmaf(p, f, 0.5f);
    p = fmaf(p, f, 1.0f);
    p = fmaf(p, f, 1.0f);
    return __int_as_float(__float_as_int(p) + (ik << 23));
}
__device__ __forceinline__ uint16_t to_fp8x2(float lo, float hi) {
    return (uint16_t)__nv_cvt_float2_to_fp8x2(make_float2(lo, hi),
                                              __NV_SATFINITE, __NV_E4M3);
}

// ------------------------- grid barrier ------------------------------------
__device__ __forceinline__ void grid_barrier() {
    __threadfence();
    __syncthreads();
    if (threadIdx.x == 0) {
        unsigned my = g_bar_gen;
        unsigned t = atomicAdd(&g_bar_cnt, 1u);
        if (t == NB_RNN - 1u) {
            g_bar_cnt = 0u;
            __threadfence();
            g_bar_gen = my + 1u;
        } else {
            while (g_bar_gen == my) { }
        }
        __threadfence();
    }
    __syncthreads();
}

// ------------------------- fused prep (launch #1) --------------------------
__global__ __launch_bounds__(256) void fused_prep(
    const int* __restrict__ tokens, const float* __restrict__ E,
    const float* __restrict__ Wi, const float* __restrict__ bi,
    const float* __restrict__ bh, const float* __restrict__ Wo,
    const float* __restrict__ bo)
{
    __shared__ float tbuf[32][33];
    const int bx = blockIdx.x, t = threadIdx.x;
    if (bx < 2048) {                       // gather -> g_Xb (bf16)
        int b = bx >> 8, tt = bx & 255;
        int tok = tokens[b * SS + tt];
        float4 v = __ldg((const float4*)(E + (size_t)tok * H) + t);
        __nv_bfloat162 lo = __float22bfloat162_rn(make_float2(v.x, v.y));
        __nv_bfloat162 hi = __float22bfloat162_rn(make_float2(v.z, v.w));
        uint2 u;
        u.x = *(uint32_t*)&lo; u.y = *(uint32_t*)&hi;
        ((uint2*)(g_Xb + (size_t)bx * H))[t] = u;
    } else if (bx < 3072) {                // Wo0 transpose -> g_Wo0Tb
        int id = bx - 2048;
        int bxt = (id & 31) * 32, byt = (id >> 5) * 32;
        int tx = t & 31, ty = t >> 5;
        for (int j = ty; j < 32; j += 8)
            tbuf[j][tx] = Wo[(size_t)(byt + j) * H + bxt + tx];
        __syncthreads();
        for (int j = ty; j < 32; j += 8)
            g_Wo0Tb[(size_t)(bxt + j) * H + byt + tx] = __float2bfloat16(tbuf[tx][j]);
    } else if (bx < 3200) {                // bias prep -> g_c1, g_b0
        int w = t >> 5, lane = t & 31;
        int r = (bx - 3072) * 8 + w;
        const float* Wi1r = Wi + (size_t)H * H + (size_t)r * H;
        float s = 0.f;
        for (int k = lane; k < H; k += 32) s += Wi1r[k] * bo[k];
        #pragma unroll
        for (int off = 16; off; off >>= 1) s += __shfl_xor_sync(0xffffffffu, s, off);
        if (lane == 0) {
            g_c1[r] = s + bi[H + r] + bh[H + r];
            g_b0[r] = bi[r] + bh[r];
        }
    } else if (bx < 4224) {                // conv Wi -> g_Wib
        int i = (bx - 3200) * 256 + t;
        const float4* p = (const float4*)Wi + (size_t)i * 2;
        float4 a = __ldg(p), b = __ldg(p + 1);
        __nv_bfloat162 r0 = __float22bfloat162_rn(make_float2(a.x, a.y));
        __nv_bfloat162 r1 = __float22bfloat162_rn(make_float2(a.z, a.w));
        __nv_bfloat162 r2 = __float22bfloat162_rn(make_float2(b.x, b.y));
        __nv_bfloat162 r3 = __float22bfloat162_rn(make_float2(b.z, b.w));
        uint4 u;
        u.x = *(uint32_t*)&r0; u.y = *(uint32_t*)&r1;
        u.z = *(uint32_t*)&r2; u.w = *(uint32_t*)&r3;
        ((uint4*)g_Wib)[i] = u;
    } else {                               // conv Wo1 -> g_Wo1b
        int i = (bx - 4224) * 256 + t;
        const float4* p = (const float4*)(Wo + (size_t)H * H) + (size_t)i * 2;
        float4 a = __ldg(p), b = __ldg(p + 1);
        __nv_bfloat162 r0 = __float22bfloat162_rn(make_float2(a.x, a.y));
        __nv_bfloat162 r1 = __float22bfloat162_rn(make_float2(a.z, a.w));
        __nv_bfloat162 r2 = __float22bfloat162_rn(make_float2(b.x, b.y));
        __nv_bfloat162 r3 = __float22bfloat162_rn(make_float2(b.z, b.w));
        uint4 u;
        u.x = *(uint32_t*)&r0; u.y = *(uint32_t*)&r1;
        u.z = *(uint32_t*)&r2; u.w = *(uint32_t*)&r3;
        ((uint4*)g_Wo1b)[i] = u;
    }
}

// ------------------------- E -> fp8 (x64) ----------------------------------
__global__ __launch_bounds__(256) void conv_fp8(const float* __restrict__ in,
                                                uint8_t* __restrict__ out, int n8) {
    int i = blockIdx.x * 256 + threadIdx.x;
    if (i >= n8) return;
    const float4* p = (const float4*)in + (size_t)i * 2;
    float4 a = __ldg(p), b = __ldg(p + 1);
    uint16_t q0 = to_fp8x2(a.x * FP8_SCALE, a.y * FP8_SCALE);
    uint16_t q1 = to_fp8x2(a.z * FP8_SCALE, a.w * FP8_SCALE);
    uint16_t q2 = to_fp8x2(b.x * FP8_SCALE, b.y * FP8_SCALE);
    uint16_t q3 = to_fp8x2(b.z * FP8_SCALE, b.w * FP8_SCALE);
    uint2 u;
    u.x = (uint32_t)q0 | ((uint32_t)q1 << 16);
    u.y = (uint32_t)q2 | ((uint32_t)q3 << 16);
    ((uint2*)out)[i] = u;
}

// ------------------------- 128x128 bf16 mma GEMM body (2-stage, occ 2) -----
// C[m][n] = bias[n] + sum_k A[m*K+k]*B[n*K+k].  Out fp32 (Cf) or fp8 x64 (C8).
#define S_LPB   80
#define S_TILEB 10240
__device__ __forceinline__ void gemm128_body(
    const __nv_bfloat16* __restrict__ A,
    const __nv_bfloat16* __restrict__ B,
    const float* __restrict__ bias,
    float* __restrict__ Cf,
    uint8_t* __restrict__ C8,
    int K, int ldc, int bx, int by, char* smem)
{
    const uint32_t sb = smem_u32(smem);
    const int tid = threadIdx.x;
    const int m0 = bx * 128, n0 = by * 128;
    const int niter = K >> 5;

    const int lrow = tid >> 1, lhalf = (tid & 1) * 16;
    const __nv_bfloat16* Ag = A + (size_t)(m0 + lrow) * K + lhalf;
    const __nv_bfloat16* Bg = B + (size_t)(n0 + lrow) * K + lhalf;
    const uint32_t sdst = (uint32_t)lrow * S_LPB + (uint32_t)lhalf * 2;

    float acc[4][4][4];
    #pragma unroll
    for (int i = 0; i < 4; i++)
        #pragma unroll
        for (int j = 0; j < 4; j++)
            #pragma unroll
            for (int q = 0; q < 4; q++) acc[i][j][q] = 0.f;

    const int w = tid >> 5, lane = tid & 31;
    const int wm = (w >> 2) * 64, wn = (w & 3) * 32;
    const int a_row = wm + ((lane >> 3) & 1) * 8 + (lane & 7);
    const int a_col8 = ((lane >> 4) & 1) * 8;
    const int b_row = wn + ((lane >> 4) & 1) * 8 + (lane & 7);
    const int b_col8 = ((lane >> 3) & 1) * 8;

    {
        cpasync16(sb + sdst, Ag);
        cpasync16(sb + sdst + 16, Ag + 8);
        cpasync16(sb + 2 * S_TILEB + sdst, Bg);
        cpasync16(sb + 2 * S_TILEB + sdst + 16, Bg + 8);
        asm volatile("cp.async.commit_group;" ::: "memory");
    }

    for (int it = 0; it < niter; ++it) {
        if (it + 1 < niter) {
            const uint32_t bo = (uint32_t)((it + 1) & 1) * S_TILEB;
            const int ko = (it + 1) * 32;
            cpasync16(sb + bo + sdst, Ag + ko);
            cpasync16(sb + bo + sdst + 16, Ag + ko + 8);
            cpasync16(sb + 2 * S_TILEB + bo + sdst, Bg + ko);
            cpasync16(sb + 2 * S_TILEB + bo + sdst + 16, Bg + ko + 8);
            asm volatile("cp.async.commit_group;" ::: "memory");
            asm volatile("cp.async.wait_group 1;" ::: "memory");
        } else {
            asm volatile("cp.async.wait_group 0;" ::: "memory");
        }
        __syncthreads();

        const uint32_t sA = sb + (uint32_t)(it & 1) * S_TILEB;
        const uint32_t sB = sA + 2 * S_TILEB;
        #pragma unroll
        for (int ks = 0; ks < 2; ++ks) {
            uint32_t af[4][4], bf[4][2];
            #pragma unroll
            for (int mf = 0; mf < 4; ++mf)
                ldmx4(af[mf], sA + (uint32_t)(a_row + mf * 16) * S_LPB
                              + (uint32_t)(ks * 16 + a_col8) * 2);
            #pragma unroll
            for (int nf2 = 0; nf2 < 2; ++nf2) {
                uint32_t r[4];
                ldmx4(r, sB + (uint32_t)(b_row + nf2 * 16) * S_LPB
                         + (uint32_t)(ks * 16 + b_col8) * 2);
                bf[nf2 * 2][0] = r[0]; bf[nf2 * 2][1] = r[1];
                bf[nf2 * 2 + 1][0] = r[2]; bf[nf2 * 2 + 1][1] = r[3];
            }
            #pragma unroll
            for (int mf = 0; mf < 4; ++mf)
                #pragma unroll
                for (int nf = 0; nf < 4; ++nf)
                    mma16816(acc[mf][nf], af[mf], bf[nf]);
        }
        __syncthreads();
    }

    const int erow = lane >> 2, ecol = (lane & 3) * 2;
    #pragma unroll
    for (int mf = 0; mf < 4; ++mf) {
        #pragma unroll
        for (int nf = 0; nf < 4; ++nf) {
            const int col = wn + nf * 8 + ecol;
            float b0v = bias ? bias[n0 + col] : 0.f;
            float b1v = bias ? bias[n0 + col + 1] : 0.f;
            float v00 = acc[mf][nf][0] + b0v, v01 = acc[mf][nf][1] + b1v;
            float v10 = acc[mf][nf][2] + b0v, v11 = acc[mf][nf][3] + b1v;
            const size_t r0 = (size_t)(m0 + wm + mf * 16 + erow);
            if (C8) {
                *(uint16_t*)(C8 + r0 * ldc + n0 + col) =
                    to_fp8x2(v00 * FP8_SCALE, v01 * FP8_SCALE);
                *(uint16_t*)(C8 + (r0 + 8) * ldc + n0 + col) =
                    to_fp8x2(v10 * FP8_SCALE, v11 * FP8_SCALE);
            } else {
                *(float2*)(Cf + r0 * ldc + n0 + col) = make_float2(v00, v01);
                *(float2*)(Cf + (r0 + 8) * ldc + n0 + col) = make_float2(v10, v11);
            }
        }
    }
}

// merged pre0 + M10 (one wave, occ 2): bx<16 -> pre0, else M10
__global__ __launch_bounds__(256, 2) void aux_gemms() {
    __shared__ __align__(16) char smem[4 * S_TILEB];
    if (blockIdx.x < 16) {
        gemm128_body(g_Xb, g_Wib, g_b0, g_pre0, nullptr, H, H,
                     blockIdx.x, blockIdx.y, smem);
    } else {
        gemm128_body(g_Wib + (size_t)H * H, g_Wo0Tb, nullptr, g_M10, nullptr, H, H,
                     blockIdx.x - 16, blockIdx.y, smem);
    }
}

// Y8 = fp8(x64)(HS1 @ Wo1.T + bo1), 128 CTAs occ 2
__global__ __launch_bounds__(256, 2) void y_gemm(const float* __restrict__ bo1) {
    __shared__ __align__(16) char smem[4 * S_TILEB];
    gemm128_body(g_HS1b, g_Wo1b, bo1, nullptr, g_Y8, H, H,
                 blockIdx.x, blockIdx.y, smem);
}

// ------------------------- fp8 logits GEMM + exp epilogue ------------------
#define LPB     80
#define ASTG    (128 * LPB)
#define BSTG    (256 * LPB)
#define STG     (ASTG + BSTG)
#define GM_SMEM (4 * STG)                 // 122880
__global__ __launch_bounds__(256, 1) void gemm_fp8_logits(
    const uint8_t* __restrict__ A,
    const uint8_t* __restrict__ B,
    float* __restrict__ out)
{
    extern __shared__ __align__(16) char smem[];
    __shared__ float sred[4][128];
    const uint32_t sb = smem_u32(smem);
    const int tid = threadIdx.x;
    const int m0 = blockIdx.x * 128, n0 = blockIdx.y * 256;
    const int niter = H >> 6;     // 16

    float acc[4][8][4];
    #pragma unroll
    for (int i = 0; i < 4; i++)
        #pragma unroll
        for (int j = 0; j < 8; j++)
            #pragma unroll
            for (int q = 0; q < 4; q++) acc[i][j][q] = 0.f;

    const int w = tid >> 5, lane = tid & 31;
    const int wm = (w >> 2) * 64, wn = (w & 3) * 64;
    const int a_row = wm + ((lane >> 3) & 1) * 8 + (lane & 7);
    const int a_col8 = ((lane >> 4) & 1) * 8;
    const int b_row = ((lane >> 4) & 1) * 8 + (lane & 7);
    const int b_col8 = ((lane >> 3) & 1) * 8;

    auto issue_stage = [&](int s, int ko) {
        const uint32_t sA = sb + (uint32_t)s * STG;
        const uint32_t sB = sA + ASTG;
        #pragma unroll
        for (int j = 0; j < 2; ++j) {
            int c = tid + 256 * j;
            int row = c >> 2, col = (c & 3) * 16;
            cpasync16(sA + (uint32_t)row * LPB + (uint32_t)(c & 3) * 16,
                      A + (size_t)(m0 + row) * H + ko + col);
        }
        #pragma unroll
        for (int j = 0; j < 4; ++j) {
            int c = tid + 256 * j;
            int row = c >> 2, col = (c & 3) * 16;
            cpasync16(sB + (uint32_t)row * LPB + (uint32_t)(c & 3) * 16,
                      B + (size_t)(n0 + row) * H + ko + col);
        }
    };

    #pragma unroll
    for (int s = 0; s < 3; ++s) {
        issue_stage(s, s * 64);
        asm volatile("cp.async.commit_group;" ::: "memory");
    }

    for (int it = 0; it < niter; ++it) {
        asm volatile("cp.async.wait_group 2;" ::: "memory");
        __syncthreads();
        if (it + 3 < niter) issue_stage((it + 3) & 3, (it + 3) * 64);
        asm volatile("cp.async.commit_group;" ::: "memory");

        const uint32_t sA = sb + (uint32_t)(it & 3) * STG;
        const uint32_t sB = sA + ASTG;
        #pragma unroll
        for (int ks = 0; ks < 2; ++ks) {
            uint32_t af[4][4], bf[8][2];
            #pragma unroll
            for (int mf = 0; mf < 4; ++mf)
                ldmx4(af[mf], sA + (uint32_t)(a_row + mf * 16) * LPB
                              + (uint32_t)(ks * 16 + a_col8) * 2);
            #pragma unroll
            for (int nf2 = 0; nf2 < 4; ++nf2) {
                uint32_t r[4];
                ldmx4(r, sB + (uint32_t)(wn + nf2 * 16 + b_row) * LPB
                         + (uint32_t)(ks * 16 + b_col8) * 2);
                bf[nf2 * 2][0] = r[0]; bf[nf2 * 2][1] = r[1];
                bf[nf2 * 2 + 1][0] = r[2]; bf[nf2 * 2 + 1][1] = r[3];
            }
            #pragma unroll
            for (int mf = 0; mf < 4; ++mf)
                #pragma unroll
                for (int nf = 0; nf < 8; ++nf)
                    mma16832f8(acc[mf][nf], af[mf], bf[nf]);
        }
    }

    const int erow = lane >> 2, ecol = (lane & 3) * 2;
    #pragma unroll
    for (int mf = 0; mf < 4; ++mf) {
        float sA = 0.f, sB = 0.f;
        #pragma unroll
        for (int nf = 0; nf < 8; ++nf) {
            const int col = wn + nf * 8 + ecol;
            float e0 = fexp(acc[mf][nf][0] * FP8_INVSQ);
            float e1 = fexp(acc[mf][nf][1] * FP8_INVSQ);
            float e2 = fexp(acc[mf][nf][2] * FP8_INVSQ);
            float e3 = fexp(acc[mf][nf][3] * FP8_INVSQ);
            const size_t r0 = (size_t)(m0 + wm + mf * 16 + erow);
            *(float2*)(out + r0 * VV + n0 + col) = make_float2(e0, e1);
            *(float2*)(out + (r0 + 8) * VV + n0 + col) = make_float2(e2, e3);
            sA += e0 + e1;
            sB += e2 + e3;
        }
        sA += __shfl_xor_sync(0xffffffffu, sA, 1);
        sA += __shfl_xor_sync(0xffffffffu, sA, 2);
        sB += __shfl_xor_sync(0xffffffffu, sB, 1);
        sB += __shfl_xor_sync(0xffffffffu, sB, 2);
        if ((lane & 3) == 0) {
            sred[w & 3][wm + mf * 16 + erow] = sA;
            sred[w & 3][wm + mf * 16 + erow + 8] = sB;
        }
    }
    __syncthreads();
    if (tid < 128) {
        float s = sred[0][tid] + sred[1][tid] + sred[2][tid] + sred[3][tid];
        g_psum[(size_t)(m0 + tid) * NTILE + blockIdx.y] = s;
    }
}

// ------------------------- persistent skewed RNN (SMEM-staged) -------------
__global__ __launch_bounds__(256, 1) void rnn_kernel(const float* __restrict__ Wh,
                                                     const float* __restrict__ pre0) {
    extern __shared__ float sm[];
    float* Wsh = sm;                       // [24][1028]
    float* hs0 = sm + 24 * 1028;           // [8][1028]
    float* hs1 = hs0 + 8 * 1028;           // [8][1028]
    float* red = hs1 + 8 * 1028;           // [8 warps][24 rows][8 b]
    const int tid = threadIdx.x;
    const int r0 = blockIdx.x * 8;

    for (int idx = tid; idx < 24 * 256; idx += 256) {
        int j = idx >> 8, c = (idx & 255) * 4;
        const float* srow;
        if (j < 8)       srow = Wh + (size_t)(r0 + j) * H;
        else if (j < 16) srow = g_M10 + (size_t)(r0 + j - 8) * H;
        else             srow = Wh + (size_t)H * H + (size_t)(r0 + j - 16) * H;
        *(float4*)(Wsh + j * 1028 + c) = __ldg((const float4*)(srow + c));
    }
    if (tid < 128) {
        int slot = tid >> 6, b = (tid >> 3) & 7, r = tid & 7;
        g_h0buf[slot * (BB * H) + b * H + r0 + r] = 0.f;
        g_h1buf[slot * (BB * H) + b * H + r0 + r] = 0.f;
    }
    grid_barrier();

    const int lane = tid & 31, w = tid >> 5;
    const int b = lane & 7, rr = lane >> 3;
    const float* h0p = hs0 + b * 1028 + w * 128;
    const float* h1p = hs1 + b * 1028 + w * 128;
    const float* w00 = Wsh + (rr * 2) * 1028 + w * 128;
    const float* w01 = Wsh + (rr * 2 + 1) * 1028 + w * 128;
    const float* w10 = Wsh + (8 + rr * 2) * 1028 + w * 128;
    const float* w11 = Wsh + (9 + rr * 2) * 1028 + w * 128;
    const float* w20 = Wsh + (16 + rr * 2) * 1028 + w * 128;
    const float* w21 = Wsh + (17 + rr * 2) * 1028 + w * 128;

    for (int tick = 0; tick <= SS; ++tick) {
        const int rs0 = (tick & 1) ^ 1, rs1 = (tick & 1);
        {
            const float* gg0 = g_h0buf + rs0 * (BB * H);
            const float* gg1 = g_h1buf + rs1 * (BB * H);
            for (int c = tid; c < 2048; c += 256) {
                int row = c >> 8, seg = (c & 255) * 4;
                *(float4*)(hs0 + row * 1028 + seg) = ldcg4(gg0 + row * H + seg);
                *(float4*)(hs1 + row * 1028 + seg) = ldcg4(gg1 + row * H + seg);
            }
        }
        __syncthreads();

        ull a00 = 0, a01 = 0, a10 = 0, a11 = 0, a20 = 0, a21 = 0;
        #pragma unroll 8
        for (int i = 0; i < 32; ++i) {
            ulonglong2 h0v = *(const ulonglong2*)(h0p + i * 4);
            ulonglong2 h1v = *(const ulonglong2*)(h1p + i * 4);
            ulonglong2 v00 = *(const ulonglong2*)(w00 + i * 4);
            ulonglong2 v01 = *(const ulonglong2*)(w01 + i * 4);
            ulonglong2 v10 = *(const ulonglong2*)(w10 + i * 4);
            ulonglong2 v11 = *(const ulonglong2*)(w11 + i * 4);
            ulonglong2 v20 = *(const ulonglong2*)(w20 + i * 4);
            ulonglong2 v21 = *(const ulonglong2*)(w21 + i * 4);
            a00 = ffma2(v00.x, h0v.x, a00); a00 = ffma2(v00.y, h0v.y, a00);
            a01 = ffma2(v01.x, h0v.x, a01); a01 = ffma2(v01.y, h0v.y, a01);
            a10 = ffma2(v10.x, h0v.x, a10); a10 = ffma2(v10.y, h0v.y, a10);
            a11 = ffma2(v11.x, h0v.x, a11); a11 = ffma2(v11.y, h0v.y, a11);
            a20 = ffma2(v20.x, h1v.x, a20); a20 = ffma2(v20.y, h1v.y, a20);
            a21 = ffma2(v21.x, h1v.x, a21); a21 = ffma2(v21.y, h1v.y, a21);
        }
        red[w * 192 + (rr * 2) * 8 + b]      = hsum2(a00);
        red[w * 192 + (rr * 2 + 1) * 8 + b]  = hsum2(a01);
        red[w * 192 + (8 + rr * 2) * 8 + b]  = hsum2(a10);
        red[w * 192 + (9 + rr * 2) * 8 + b]  = hsum2(a11);
        red[w * 192 + (16 + rr * 2) * 8 + b] = hsum2(a20);
        red[w * 192 + (17 + rr * 2) * 8 + b] = hsum2(a21);
        __syncthreads();

        if (tid < 64) {
            if (tick < SS) {
                int row = tid >> 3, bb = tid & 7;
                float s = 0.f;
                #pragma unroll
                for (int ww = 0; ww < 8; ++ww) s += red[ww * 192 + row * 8 + bb];
                float v = tanhf(pre0[(size_t)(bb * SS + tick) * H + r0 + row] + s);
                __stcg(&g_h0buf[rs1 * (BB * H) + bb * H + r0 + row], v);
            }
        } else if (tid < 128) {
            if (tick >= 1) {
                int j = tid - 64, row = j >> 3, bb = j & 7;
                float s1 = 0.f, s2 = 0.f;
                #pragma unroll
                for (int ww = 0; ww < 8; ++ww) {
                    s1 += red[ww * 192 + (8 + row) * 8 + bb];
                    s2 += red[ww * 192 + (16 + row) * 8 + bb];
                }
                float v = tanhf(g_c1[r0 + row] + s1 + s2);
                __stcg(&g_h1buf[rs0 * (BB * H) + bb * H + r0 + row], v);
                g_HS1b[(size_t)(bb * SS + tick - 1) * H + r0 + row] = __float2bfloat16(v);
            }
        }
        grid_barrier();
    }
}

// ------------------------- normalize (softmax finish) ----------------------
__global__ __launch_bounds__(256) void normalize_kernel(float* __restrict__ out) {
    __shared__ float sh[256];
    const int row = blockIdx.x, t = threadIdx.x;
    sh[t] = (t < NTILE) ? g_psum[(size_t)row * NTILE + t] : 0.f;
    __syncthreads();
    #pragma unroll
    for (int s = 128; s; s >>= 1) {
        if (t < s) sh[t] += sh[t + s];
        __syncthreads();
    }
    const float inv = 1.0f / sh[0];
    float4* o = (float4*)(out + (size_t)row * VV);
    for (int i = t; i < VV / 4; i += 256) {
        float4 v = o[i];
        v.x *= inv; v.y *= inv; v.z *= inv; v.w *= inv;
        o[i] = v;
    }
}

// ------------------------- launch ------------------------------------------
extern "C" void kernel_launch(void* const* d_in, const int* in_sizes, int n_in,
                              void* d_out, int out_size) {
    const int*   tokens = (const int*)d_in[0];
    const float* E  = (const float*)d_in[1];
    const float* Wi = (const float*)d_in[2];
    const float* bi = (const float*)d_in[3];
    const float* Wh = (const float*)d_in[4];
    const float* bh = (const float*)d_in[5];
    const float* Wo = (const float*)d_in[6];
    const float* bo = (const float*)d_in[7];
    float* out = (float*)d_out;

    cudaFuncSetAttribute(rnn_kernel, cudaFuncAttributeMaxDynamicSharedMemorySize, RNN_SMEM);
    cudaFuncSetAttribute(gemm_fp8_logits, cudaFuncAttributeMaxDynamicSharedMemorySize, GM_SMEM);

    static float *pPre0 = nullptr;
    static uint8_t *pE8, *pY8;
    if (!pPre0) {
        cudaGetSymbolAddress((void**)&pPre0, g_pre0);
        cudaGetSymbolAddress((void**)&pE8,   g_E8);
        cudaGetSymbolAddress((void**)&pY8,   g_Y8);
    }

    // 1: all small prep work fused
    fused_prep<<<4736, 256>>>(tokens, E, Wi, bi, bh, Wo, bo);
    // 2: pre0 + M10 merged (192 CTAs, occ 2 -> one wave)
    aux_gemms<<<dim3(24, 8), 256>>>();
    // 3: recurrence -> g_HS1b (bf16)
    rnn_kernel<<<NB_RNN, 256, RNN_SMEM>>>(Wh, pPre0);
    // 4: Y8 = fp8(x64)(HS1 @ Wo1.T + bo1)   [profiled launch]
    y_gemm<<<dim3(16, 8), 256>>>(bo + H);
    // 5: E -> fp8 (x64)
    conv_fp8<<<(VV * H / 8 + 255) / 256, 256>>>(E, pE8, VV * H / 8);
    // 6: out = exp((Y8 @ E8^T)/4096), psum partials
    gemm_fp8_logits<<<dim3(16, NTILE), 256, GM_SMEM>>>(pY8, pE8, out);
    // 7: normalize rows
    normalize_kernel<<<MALL, 256>>>(out);
}